// round 9
// baseline (speedup 1.0000x reference)
#include <cuda_runtime.h>
#include <math.h>
#include <stdint.h>

#define CB 2
#define CL 2048
#define CD 1024
#define CNH 16
#define CHD 64
#define CM (CB*CL)          // 4096 rows
#define CHGATE 256
#define CHNU 128

// ---------------- scratch (device globals; allocation-free rule) ----------------
__device__ float g_pool[CM*CD];
__device__ float g_Q[CM*CD];
__device__ float g_K[CM*CD];
__device__ float g_V[CM*CD];
__device__ float g_gk[CM*CD];
__device__ float g_zglu[CM*CD];
__device__ float g_U[CM*CD];
__device__ float g_Gg[CM*CD];     // GLU gate branch
__device__ float g_ao[CM*CD];     // attention output
__device__ float g_zr[CM*CD];     // tf32-rounded z
__device__ float g_Wr[7*1048576 + 393216]; // transposed+rounded weights [N,K]
__device__ float g_gb[CB*CL*CL];  // coherence bias
__device__ float g_S[134217728];  // (B,NH,L,L) logits/probs (also MLP hidden scratch)
__device__ float g_gate[CM];
__device__ float g_nu[CM];
__device__ float g_csum[CB*32*CD];// pool chunk sums
__device__ float g_ctab[3*CL*1024]; // rope tables: [base][t][cos512|sin512]
__device__ double g_invd[1536];   // inv freqs: [fast | slow | glu] x 512

// ---------------- tf32 helpers ----------------
__device__ __forceinline__ unsigned f2tf(float x) {
    unsigned r; asm("cvt.rna.tf32.f32 %0, %1;" : "=r"(r) : "f"(x)); return r;
}
__device__ __forceinline__ float tfr(float x) { return __uint_as_float(f2tf(x)); }
__device__ __forceinline__ void cpa16(float* s, const float* g) {
    unsigned sa = (unsigned)__cvta_generic_to_shared(s);
    asm volatile("cp.async.cg.shared.global [%0], [%1], 16;" :: "r"(sa), "l"(g));
}
__device__ __forceinline__ void mma8(float* d, const unsigned* a, const unsigned* b) {
    asm volatile(
        "mma.sync.aligned.m16n8k8.row.col.f32.tf32.tf32.f32 "
        "{%0,%1,%2,%3},{%4,%5,%6,%7},{%8,%9},{%0,%1,%2,%3};"
        : "+f"(d[0]), "+f"(d[1]), "+f"(d[2]), "+f"(d[3])
        : "r"(a[0]), "r"(a[1]), "r"(a[2]), "r"(a[3]), "r"(b[0]), "r"(b[1]));
}
// one x4 ldmatrix: four 8x4-float tiles -> 4 regs with (row=t/4, col=t%4) mapping
__device__ __forceinline__ void ldsm4(unsigned* r, unsigned addr) {
    asm volatile("ldmatrix.sync.aligned.m8n8.x4.shared.b16 {%0,%1,%2,%3}, [%4];"
        : "=r"(r[0]), "=r"(r[1]), "=r"(r[2]), "=r"(r[3]) : "r"(addr));
}

// ---------------- weight transpose + tf32 round: W[1024,N] -> WT[N,1024] ----------------
struct TrArgs { const float* src[9]; float* dst[9]; int N[9]; };
__global__ void wtrans_kernel(TrArgs a) {
    const int w = blockIdx.z;
    const int N = a.N[w];
    const int nx = blockIdx.x * 32;
    if (nx >= N) return;
    const int ky = blockIdx.y * 32;
    __shared__ float t[32][33];
    const float* src = a.src[w];
    const int tx = threadIdx.x, ty = threadIdx.y;   // 32 x 8
#pragma unroll
    for (int i = 0; i < 4; i++)
        t[ty + 8*i][tx] = src[(size_t)(ky + ty + 8*i) * N + nx + tx];
    __syncthreads();
    float* dst = a.dst[w];
#pragma unroll
    for (int i = 0; i < 4; i++)
        dst[(size_t)(nx + ty + 8*i) * 1024 + ky + tx] = tfr(t[tx][ty + 8*i]);
}

__global__ void round_kernel(float* __restrict__ dst, const float* __restrict__ src, int n) {
    for (int i = blockIdx.x * blockDim.x + threadIdx.x; i < n; i += gridDim.x * blockDim.x)
        dst[i] = tfr(src[i]);
}

// ---------------- tensor-core GEMM: 128x128x32 tiles, tf32, full-LDSM ----------------
// C = A[M,K] @ B[N,K]^T   (both operands K-major)
// MODE 0: C = acc + bias(optional); RND: round output to tf32
// MODE 1: C = r1 + 0.42*r2 + 1.07*(acc + bias)
// MODE 2: C = tanh(gamma)/32 * acc
// MODE 3: C = 0.125*acc + gb[l,m], causal blockskip
template<int MODE, int RND>
__global__ __launch_bounds__(256, 2) void tc_gemm(
    const float* __restrict__ A, const float* __restrict__ Bm,
    const float* __restrict__ bias, float* __restrict__ C,
    int K, int lda, int ldb, int ldc,
    long sAo, long sAi, long sBo, long sBi, long sCz, long sGo, int zdiv,
    const float* __restrict__ r1, const float* __restrict__ r2,
    const float* __restrict__ gamma, const float* __restrict__ gbb)
{
    const int bm = blockIdx.y * 128, bn = blockIdx.x * 128;
    if (MODE == 3 && bn >= bm + 128) return;
    const int z = blockIdx.z;
    const int zo = z / zdiv, zi = z - zo * zdiv;
    A  += (size_t)zo * sAo + (size_t)zi * sAi;
    Bm += (size_t)zo * sBo + (size_t)zi * sBi;
    C  += (size_t)z * sCz;
    const float* gbp = (MODE == 3) ? (gbb + (size_t)zo * sGo) : nullptr;

    extern __shared__ float sm[];
    const int STG = 9216;
    float* Asm[2] = { sm, sm + STG };
    float* Bsm[2] = { sm + 4608, sm + STG + 4608 };

    const int t = threadIdx.x;
    const int wid = t >> 5, lane = t & 31;
    const int wm = (wid >> 2) * 64, wn = (wid & 3) * 32;
    const int g = lane >> 2, tig = lane & 3;

    // LDSM per-lane byte offsets (stride-36 float rows)
    const unsigned aoff = ((lane & 15) * 36 + (lane >> 4) * 4) * 4;
    const unsigned boff = ((lane & 7) * 36 + ((lane >> 3) & 1) * 4 + (lane >> 4) * (8 * 36)) * 4;

    float acc[4][4][4];
#pragma unroll
    for (int i = 0; i < 4; i++)
#pragma unroll
        for (int j = 0; j < 4; j++)
#pragma unroll
            for (int q = 0; q < 4; q++) acc[i][j][q] = 0.f;

    auto loadT = [&](float* s, const float* G, int ld, int base, int k0) {
        int r = t >> 3, k4 = (t & 7) * 4;
#pragma unroll
        for (int it = 0; it < 4; it++)
            cpa16(s + (r + it*32)*36 + k4,
                  G + (size_t)(base + r + it*32) * ld + k0 + k4);
    };

    const int NT = K >> 5;
    loadT(Asm[0], A, lda, bm, 0);
    loadT(Bsm[0], Bm, ldb, bn, 0);
    asm volatile("cp.async.commit_group;");

    for (int kt = 0; kt < NT; kt++) {
        asm volatile("cp.async.wait_group 0;");
        __syncthreads();
        if (kt + 1 < NT) {
            loadT(Asm[(kt+1)&1], A, lda, bm, (kt+1)*32);
            loadT(Bsm[(kt+1)&1], Bm, ldb, bn, (kt+1)*32);
            asm volatile("cp.async.commit_group;");
        }
        const unsigned Au = (unsigned)__cvta_generic_to_shared(Asm[kt&1]);
        const unsigned Bu = (unsigned)__cvta_generic_to_shared(Bsm[kt&1]);
#pragma unroll
        for (int ks = 0; ks < 4; ks++) {
            const int k = ks * 8;
            unsigned af[4][4];
#pragma unroll
            for (int i = 0; i < 4; i++)
                ldsm4(af[i], Au + ((wm + 16*i) * 36 + k) * 4 + aoff);
            unsigned bf[4][2];
#pragma unroll
            for (int jj = 0; jj < 2; jj++) {
                unsigned r4[4];
                ldsm4(r4, Bu + ((wn + 16*jj) * 36 + k) * 4 + boff);
                bf[2*jj][0]   = r4[0];
                bf[2*jj][1]   = r4[1];
                bf[2*jj+1][0] = r4[2];
                bf[2*jj+1][1] = r4[3];
            }
#pragma unroll
            for (int i = 0; i < 4; i++)
#pragma unroll
                for (int j = 0; j < 4; j++)
                    mma8(acc[i][j], af[i], bf[j]);
        }
    }

    float scale = 1.f;
    if (MODE == 2) scale = tanhf(gamma[0]) * 0.03125f;
    if (MODE == 3) scale = 0.125f;
#pragma unroll
    for (int i = 0; i < 4; i++) {
        const int r0 = bm + wm + 16*i + g;
#pragma unroll
        for (int j = 0; j < 4; j++) {
            const int c0 = bn + wn + 8*j + 2*tig;
#pragma unroll
            for (int h2 = 0; h2 < 2; h2++) {
                const int rr = r0 + h2*8;
                float v0 = acc[i][j][h2*2], v1 = acc[i][j][h2*2+1];
                const size_t off = (size_t)rr * ldc + c0;
                if (MODE == 0) {
                    if (bias) { v0 += bias[c0]; v1 += bias[c0+1]; }
                    if (RND) { v0 = tfr(v0); v1 = tfr(v1); }
                    C[off] = v0; C[off+1] = v1;
                } else if (MODE == 1) {
                    C[off]   = r1[off]   + 0.42f*r2[off]   + 1.07f*(v0 + bias[c0]);
                    C[off+1] = r1[off+1] + 0.42f*r2[off+1] + 1.07f*(v1 + bias[c0+1]);
                } else if (MODE == 2) {
                    C[off] = tfr(v0*scale); C[off+1] = tfr(v1*scale);
                } else {
                    const size_t go = (size_t)rr * CL + c0;
                    C[off]   = v0*scale + gbp[go];
                    C[off+1] = v1*scale + gbp[go+1];
                }
            }
        }
    }
}

// ---------------- attn_out = P @ V on tensor cores (per head, causal) ----------------
__global__ __launch_bounds__(256, 2) void attn_pv() {
    const int l0 = blockIdx.x * 128;
    const int h = blockIdx.y, b = blockIdx.z;
    const float* S = g_S + ((size_t)(b * CNH + h)) * CL * CL;
    const float* V = g_V + (size_t)b * CL * CD + h * CHD;
    float* O = g_ao + (size_t)b * CL * CD + h * CHD;

    extern __shared__ float sm[];
    const int STG = 4608 + 2304;
    float* Ssm[2] = { sm, sm + STG };
    float* Vsm[2] = { sm + 4608, sm + STG + 4608 };

    const int t = threadIdx.x;
    const int wid = t >> 5, lane = t & 31;
    const int wm = wid * 16;
    const int g = lane >> 2, tig = lane & 3;
    const unsigned aoff = ((lane & 15) * 36 + (lane >> 4) * 4) * 4;

    float acc[8][4];
#pragma unroll
    for (int j = 0; j < 8; j++)
#pragma unroll
        for (int q = 0; q < 4; q++) acc[j][q] = 0.f;

    auto loadS = [&](float* s, int k0) {
        int r = t >> 3, k4 = (t & 7) * 4;
#pragma unroll
        for (int it = 0; it < 4; it++)
            cpa16(s + (r + it*32)*36 + k4,
                  S + (size_t)(l0 + r + it*32) * CL + k0 + k4);
    };
    auto loadV = [&](float* s, int k0) {
        int kr = t >> 4, n4 = (t & 15) * 4;
#pragma unroll
        for (int it = 0; it < 2; it++)
            cpa16(s + (kr + it*16)*72 + n4,
                  V + (size_t)(k0 + kr + it*16) * CD + n4);
    };

    const int NT = (l0 + 128) >> 5;
    loadS(Ssm[0], 0); loadV(Vsm[0], 0);
    asm volatile("cp.async.commit_group;");

    for (int kt = 0; kt < NT; kt++) {
        asm volatile("cp.async.wait_group 0;");
        __syncthreads();
        if (kt + 1 < NT) {
            loadS(Ssm[(kt+1)&1], (kt+1)*32);
            loadV(Vsm[(kt+1)&1], (kt+1)*32);
            asm volatile("cp.async.commit_group;");
        }
        const unsigned Su = (unsigned)__cvta_generic_to_shared(Ssm[kt&1]);
        const unsigned* Bb = (const unsigned*)Vsm[kt&1];
#pragma unroll
        for (int ks = 0; ks < 4; ks++) {
            const int k = ks * 8;
            unsigned af[4];
            ldsm4(af, Su + (wm * 36 + k) * 4 + aoff);
            unsigned bf[8][2];
#pragma unroll
            for (int j = 0; j < 8; j++) {
                const unsigned* bp = Bb + (k + tig)*72 + 8*j + g;
                bf[j][0] = bp[0];
                bf[j][1] = bp[4*72];
            }
#pragma unroll
            for (int j = 0; j < 8; j++)
                mma8(acc[j], af, bf[j]);
        }
    }
#pragma unroll
    for (int j = 0; j < 8; j++) {
        const int c0 = 8*j + 2*tig;
#pragma unroll
        for (int h2 = 0; h2 < 2; h2++) {
            const int rr = l0 + wm + g + h2*8;
            O[(size_t)rr * CD + c0]     = acc[j][h2*2];
            O[(size_t)rr * CD + c0 + 1] = acc[j][h2*2 + 1];
        }
    }
}

// ---------------- rope helpers ----------------
__global__ void inv_kernel() {
    int d = threadIdx.x;
    double e = (double)(2 * d) / (double)CD;
    g_invd[d]        = pow(1.6180339887498948482, -e);
    g_invd[512 + d]  = pow(1618.0, -e);
    g_invd[1024 + d] = pow(16180.0, -e);
}

__device__ __forceinline__ void rope_cs(double inv, int t, float* c, float* s) {
    double ang = (double)t * inv;
    double k = floor(ang * 0.15915494309189533576888376337251436);
    float a = (float)(ang - k * 6.28318530717958647692528676655900577);
    sincosf(a, s, c);
}

// rope tables: one DP evaluation per (base,t,d); layout [base][t][cos512|sin512]
__global__ void ctab_kernel() {
    int idx = blockIdx.x * blockDim.x + threadIdx.x;   // 3*2048*512
    int d = idx & 511;
    int t = (idx >> 9) & (CL - 1);
    int base = idx >> 20;
    float c, s;
    rope_cs(g_invd[base * 512 + d], t, &c, &s);
    float* o = g_ctab + (size_t)base * CL * 1024 + t * 1024;
    o[d] = c;
    o[d + 512] = s;
}

// ---------------- causal cumulative mean: 3-phase parallel scan ----------------
__global__ void poolA_kernel(const float* __restrict__ z) {
    const int c = blockIdx.x, b = blockIdx.y;
    const int t = threadIdx.x;
    const float4* zp = (const float4*)(z + ((size_t)b * CL + c * 64) * CD);
    float4* pp = (float4*)(g_pool + ((size_t)b * CL + c * 64) * CD);
    float4 acc = make_float4(0.f, 0.f, 0.f, 0.f);
    for (int r = 0; r < 64; r++) {
        float4 v = zp[r * 256 + t];
        acc.x += v.x; acc.y += v.y; acc.z += v.z; acc.w += v.w;
        pp[r * 256 + t] = acc;
    }
    ((float4*)g_csum)[((size_t)b * 32 + c) * 256 + t] = acc;
}
__global__ void poolB_kernel() {
    int idx = blockIdx.x * 256 + threadIdx.x;
    int b = idx >> 10, d = idx & 1023;
    float run = 0.f;
    for (int c = 0; c < 32; c++) {
        size_t o = ((size_t)b * 32 + c) * CD + d;
        float v = g_csum[o];
        g_csum[o] = run;
        run += v;
    }
}
__global__ void poolC_kernel() {
    size_t idx = (size_t)blockIdx.x * 256 + threadIdx.x;
    int row = (int)(idx >> 8);
    int f4 = (int)(idx & 255);
    int b = row >> 11, l = row & (CL - 1), c = l >> 6;
    float4 off = ((const float4*)g_csum)[((size_t)(b * 32 + c)) * 256 + f4];
    float4 v = ((float4*)g_pool)[idx];
    float inv = 1.f / (float)(l + 1);
    v.x = tfr((v.x + off.x) * inv);
    v.y = tfr((v.y + off.y) * inv);
    v.z = tfr((v.z + off.z) * inv);
    v.w = tfr((v.w + off.w) * inv);
    ((float4*)g_pool)[idx] = v;
}

// ---------------- gate/nu epilogues ----------------
__global__ __launch_bounds__(256) void gate2_kernel(
    const float* __restrict__ hid, const float* __restrict__ w2,
    const float* __restrict__ b2)
{
    int row = blockIdx.x * 8 + (threadIdx.x >> 5);
    int lane = threadIdx.x & 31;
    const float* hr = hid + (size_t)row * CHGATE;
    float acc = 0.f;
#pragma unroll
    for (int j = 0; j < 8; j++) {
        int c = lane + j * 32;
        float x = hr[c];
        float h = 0.5f * x * (1.f + erff(x * 0.7071067811865476f));
        acc += h * w2[c];
    }
#pragma unroll
    for (int o = 16; o > 0; o >>= 1) acc += __shfl_xor_sync(~0u, acc, o);
    if (lane == 0) {
        float y = acc + b2[0];
        g_gate[row] = 1.f / (1.f + expf(-y));
    }
}
__global__ __launch_bounds__(256) void nu2_kernel(
    const float* __restrict__ hid, const float* __restrict__ w2,
    const float* __restrict__ b2,
    const float* __restrict__ nu_diff, const float* __restrict__ nu_adv)
{
    int row = blockIdx.x * 8 + (threadIdx.x >> 5);
    int lane = threadIdx.x & 31;
    const float* hr = hid + (size_t)row * CHNU;
    float acc = 0.f;
#pragma unroll
    for (int j = 0; j < 4; j++) {
        int c = lane + j * 32;
        acc += tanhf(hr[c]) * w2[c];
    }
#pragma unroll
    for (int o = 16; o > 0; o >>= 1) acc += __shfl_xor_sync(~0u, acc, o);
    if (lane == 0) {
        g_nu[row] = fabsf(nu_diff[0]) + tanhf(acc + b2[0]) * fabsf(nu_adv[0]);
    }
}

// ---------------- merged RoPE from tables: Q/K in-place + zglu write ----------------
__global__ void rope_all_kernel(const float* __restrict__ z) {
    int idx = blockIdx.x * blockDim.x + threadIdx.x;
    if (idx >= CM * 512) return;
    int d = idx & 511;
    int row = idx >> 9;
    int t = row & (CL - 1);
    float g = g_gate[row];
    const float* tf = g_ctab + (size_t)t * 1024 + d;
    const float* ts = tf + (size_t)CL * 1024;
    const float* tg = ts + (size_t)CL * 1024;
    float c = g * tf[0] + (1.f - g) * ts[0];
    float s = g * tf[512] + (1.f - g) * ts[512];
    float cg = tg[0], sg = tg[512];
    size_t lo = (size_t)row * CD + d, hi = lo + 512;
    float ql = g_Q[lo], qh = g_Q[hi];
    g_Q[lo] = tfr(ql * c - qh * s);
    g_Q[hi] = tfr(qh * c + ql * s);
    float kl = g_K[lo], kh = g_K[hi];
    g_K[lo] = tfr(kl * c - kh * s);
    g_K[hi] = tfr(kh * c + kl * s);
    float xl = z[lo], xh = z[hi];
    g_zglu[lo] = tfr(xl * cg - xh * sg);
    g_zglu[hi] = tfr(xh * cg + xl * sg);
}

// ---------------- fused causal softmax (16 heads serial) + head-mean, float4 ----------------
__global__ __launch_bounds__(256) void smaw_kernel(float* __restrict__ aw) {
    const int l = blockIdx.x;
    const int b = blockIdx.y;
    const int n = l + 1;
    const int bound = ((l >> 7) + 1) << 7;     // 128-block boundary for attn_pv
    const int tid = threadIdx.x;
    const int lane = tid & 31, wid = tid >> 5;
    __shared__ float red[8];
    float4 awacc[2];
    awacc[0] = make_float4(0.f, 0.f, 0.f, 0.f);
    awacc[1] = make_float4(0.f, 0.f, 0.f, 0.f);
    const float NEG = -3.4e38f;

    for (int h = 0; h < CNH; h++) {
        float* row = g_S + ((size_t)(b * CNH + h) * CL + l) * CL;
        float4* row4 = (float4*)row;
        float4 v[2];
        float mx = NEG;
#pragma unroll
        for (int ii = 0; ii < 2; ii++) {
            int f4 = tid + ii * 256;
            int c0 = f4 * 4;
            if (c0 < n) {
                float4 tv = row4[f4];
                if (c0 + 1 >= n) tv.y = NEG;
                if (c0 + 2 >= n) tv.z = NEG;
                if (c0 + 3 >= n) tv.w = NEG;
                v[ii] = tv;
            } else {
                v[ii] = make_float4(NEG, NEG, NEG, NEG);
            }
            mx = fmaxf(mx, fmaxf(fmaxf(v[ii].x, v[ii].y), fmaxf(v[ii].z, v[ii].w)));
        }
#pragma unroll
        for (int o = 16; o > 0; o >>= 1) mx = fmaxf(mx, __shfl_xor_sync(~0u, mx, o));
        if (lane == 0) red[wid] = mx;
        __syncthreads();
        mx = red[0];
#pragma unroll
        for (int w = 1; w < 8; w++) mx = fmaxf(mx, red[w]);
        __syncthreads();

        float sum = 0.f;
#pragma unroll
        for (int ii = 0; ii < 2; ii++) {
            v[ii].x = expf(v[ii].x - mx);
            v[ii].y = expf(v[ii].y - mx);
            v[ii].z = expf(v[ii].z - mx);
            v[ii].w = expf(v[ii].w - mx);
            sum += v[ii].x + v[ii].y + v[ii].z + v[ii].w;
        }
#pragma unroll
        for (int o = 16; o > 0; o >>= 1) sum += __shfl_xor_sync(~0u, sum, o);
        if (lane == 0) red[wid] = sum;
        __syncthreads();
        sum = red[0];
#pragma unroll
        for (int w = 1; w < 8; w++) sum += red[w];
        __syncthreads();
        float rinv = 1.f / sum;

#pragma unroll
        for (int ii = 0; ii < 2; ii++) {
            int f4 = tid + ii * 256;
            int c0 = f4 * 4;
            if (c0 < bound) {
                float4 p;
                p.x = v[ii].x * rinv; p.y = v[ii].y * rinv;
                p.z = v[ii].z * rinv; p.w = v[ii].w * rinv;
                awacc[ii].x += p.x; awacc[ii].y += p.y;
                awacc[ii].z += p.z; awacc[ii].w += p.w;
                float4 pr;
                pr.x = tfr(p.x); pr.y = tfr(p.y); pr.z = tfr(p.z); pr.w = tfr(p.w);
                row4[f4] = pr;
            }
        }
    }
    float4* awr4 = (float4*)(aw + ((size_t)b * CL + l) * CL);
    const float s16 = 1.f / CNH;
#pragma unroll
    for (int ii = 0; ii < 2; ii++) {
        int f4 = tid + ii * 256;
        float4 o;
        o.x = awacc[ii].x * s16; o.y = awacc[ii].y * s16;
        o.z = awacc[ii].z * s16; o.w = awacc[ii].w * s16;
        awr4[f4] = o;
    }
}

// ---------------- bilinear * (-nu) + LayerNorm (rounded out) ----------------
__global__ __launch_bounds__(256) void bilin_ln_kernel(
    const float* __restrict__ ln_w, const float* __restrict__ ln_b)
{
    int row = blockIdx.x;
    int tid = threadIdx.x;
    size_t off = (size_t)row * CD;
    float nu = g_nu[row];
    __shared__ float red[256], red2[256];
    float a[4]; float s = 0.f, s2 = 0.f;
#pragma unroll
    for (int i = 0; i < 4; i++) {
        int d = tid + i * 256;
        float v = -nu * g_U[off + d] * g_Gg[off + d];
        a[i] = v; s += v; s2 += v * v;
    }
    red[tid] = s; red2[tid] = s2; __syncthreads();
    for (int st = 128; st > 0; st >>= 1) {
        if (tid < st) { red[tid] += red[tid + st]; red2[tid] += red2[tid + st]; }
        __syncthreads();
    }
    float mu = red[0] * (1.f / CD);
    float var = red2[0] * (1.f / CD) - mu * mu;
    float rstd = rsqrtf(var + 1e-5f);
#pragma unroll
    for (int i = 0; i < 4; i++) {
        int d = tid + i * 256;
        g_U[off + d] = tfr((a[i] - mu) * rstd * ln_w[d] + ln_b[d]);
    }
}

// ---------------- launcher ----------------
extern "C" void kernel_launch(void* const* d_in, const int* in_sizes, int n_in,
                              void* d_out, int out_size) {
    (void)in_sizes; (void)n_in; (void)out_size;
    const float* z     = (const float*)d_in[0];
    const float* Wq    = (const float*)d_in[1];
    const float* bq    = (const float*)d_in[2];
    const float* Wk    = (const float*)d_in[3];
    const float* bk    = (const float*)d_in[4];
    const float* Wv    = (const float*)d_in[5];
    const float* bv    = (const float*)d_in[6];
    const float* Wcoh  = (const float*)d_in[7];
    const float* gamma = (const float*)d_in[8];
    const float* rg_w1 = (const float*)d_in[9];
    const float* rg_b1 = (const float*)d_in[10];
    const float* rg_w2 = (const float*)d_in[11];
    const float* rg_b2 = (const float*)d_in[12];
    const float* nu_diff = (const float*)d_in[13];
    const float* nu_adv  = (const float*)d_in[14];
    const float* nu_w1 = (const float*)d_in[15];
    const float* nu_b1 = (const float*)d_in[16];
    const float* nu_w2 = (const float*)d_in[17];
    const float* nu_b2 = (const float*)d_in[18];
    const float* Wu    = (const float*)d_in[19];
    const float* bu    = (const float*)d_in[20];
    const float* Wg    = (const float*)d_in[21];
    const float* bg    = (const float*)d_in[22];
    const float* ln_w  = (const float*)d_in[23];
    const float* ln_b  = (const float*)d_in[24];
    const float* Cw    = (const float*)d_in[25];
    const float* Cb    = (const float*)d_in[26];

    float* out_z  = (float*)d_out;
    float* out_aw = out_z + (size_t)CM * CD;

    void* tmp;
    cudaGetSymbolAddress(&tmp, g_pool); float* pPool = (float*)tmp;
    cudaGetSymbolAddress(&tmp, g_Q);    float* pQ    = (float*)tmp;
    cudaGetSymbolAddress(&tmp, g_K);    float* pK    = (float*)tmp;
    cudaGetSymbolAddress(&tmp, g_V);    float* pV    = (float*)tmp;
    cudaGetSymbolAddress(&tmp, g_gk);   float* pGk   = (float*)tmp;
    cudaGetSymbolAddress(&tmp, g_zglu); float* pZg   = (float*)tmp;
    cudaGetSymbolAddress(&tmp, g_U);    float* pU    = (float*)tmp;
    cudaGetSymbolAddress(&tmp, g_Gg);   float* pG    = (float*)tmp;
    cudaGetSymbolAddress(&tmp, g_ao);   float* pAo   = (float*)tmp;
    cudaGetSymbolAddress(&tmp, g_zr);   float* pZr   = (float*)tmp;
    cudaGetSymbolAddress(&tmp, g_Wr);   float* pWr   = (float*)tmp;
    cudaGetSymbolAddress(&tmp, g_gb);   float* pGb   = (float*)tmp;
    cudaGetSymbolAddress(&tmp, g_S);    float* pS    = (float*)tmp;

    float* rWq = pWr;                         // all transposed [N,K=1024]
    float* rWk = pWr + 1048576;
    float* rWv = pWr + 2*1048576;
    float* rWc = pWr + 3*1048576;
    float* rWu = pWr + 4*1048576;
    float* rWg = pWr + 5*1048576;
    float* rCw = pWr + 6*1048576;
    float* rG1 = pWr + 7*1048576;             // rg_w1^T (256 x 1024)
    float* rN1 = pWr + 7*1048576 + 262144;    // nu_w1^T (128 x 1024)

    float* pHg = pS;                          // gate hidden (CM x 256) in g_S scratch
    float* pHn = pS + (size_t)CM * CHGATE;    // nu hidden   (CM x 128)

    const size_t SMEM  = 2 * 9216 * sizeof(float);   // 73728
    const size_t SMEMP = 2 * 6912 * sizeof(float);   // 55296 (attn_pv)
    cudaFuncSetAttribute(tc_gemm<0,0>, cudaFuncAttributeMaxDynamicSharedMemorySize, (int)SMEM);
    cudaFuncSetAttribute(tc_gemm<0,1>, cudaFuncAttributeMaxDynamicSharedMemorySize, (int)SMEM);
    cudaFuncSetAttribute(tc_gemm<1,0>, cudaFuncAttributeMaxDynamicSharedMemorySize, (int)SMEM);
    cudaFuncSetAttribute(tc_gemm<2,0>, cudaFuncAttributeMaxDynamicSharedMemorySize, (int)SMEM);
    cudaFuncSetAttribute(tc_gemm<3,0>, cudaFuncAttributeMaxDynamicSharedMemorySize, (int)SMEM);
    cudaFuncSetAttribute(attn_pv, cudaFuncAttributeMaxDynamicSharedMemorySize, (int)SMEMP);

    dim3 gmain(CD / 128, CM / 128, 1);   // (8, 32)

    inv_kernel<<<1, 512>>>();                                        // 1

    TrArgs ta;
    ta.src[0]=Wq;   ta.dst[0]=rWq; ta.N[0]=1024;
    ta.src[1]=Wk;   ta.dst[1]=rWk; ta.N[1]=1024;
    ta.src[2]=Wv;   ta.dst[2]=rWv; ta.N[2]=1024;
    ta.src[3]=Wcoh; ta.dst[3]=rWc; ta.N[3]=1024;
    ta.src[4]=Wu;   ta.dst[4]=rWu; ta.N[4]=1024;
    ta.src[5]=Wg;   ta.dst[5]=rWg; ta.N[5]=1024;
    ta.src[6]=Cw;   ta.dst[6]=rCw; ta.N[6]=1024;
    ta.src[7]=rg_w1;ta.dst[7]=rG1; ta.N[7]=256;
    ta.src[8]=nu_w1;ta.dst[8]=rN1; ta.N[8]=128;
    wtrans_kernel<<<dim3(32, 32, 9), dim3(32, 8)>>>(ta);             // 2
    round_kernel<<<2048, 256>>>(pZr, z, CM*CD);                      // 3

    // Q/K/V GEMMs early: launches 4-6 so ncu (-s 5 -c 1) captures a tc_gemm
    tc_gemm<0,0><<<gmain, 256, SMEM>>>(pZr, rWq, bq, pQ, CD, CD, CD, CD,    // 4
        0,0,0,0,0,0,1, nullptr, nullptr, nullptr, nullptr);
    tc_gemm<0,1><<<gmain, 256, SMEM>>>(pZr, rWk, bk, pK, CD, CD, CD, CD,    // 5
        0,0,0,0,0,0,1, nullptr, nullptr, nullptr, nullptr);
    tc_gemm<0,1><<<gmain, 256, SMEM>>>(pZr, rWv, bv, pV, CD, CD, CD, CD,    // 6
        0,0,0,0,0,0,1, nullptr, nullptr, nullptr, nullptr);

    poolA_kernel<<<dim3(32, CB), 256>>>(z);                          // 7
    poolB_kernel<<<8, 256>>>();                                      // 8
    poolC_kernel<<<CM, 256>>>();                                     // 9
    ctab_kernel<<<(3 * CL * 512) / 256, 256>>>();                    // 10

    tc_gemm<0,1><<<gmain, 256, SMEM>>>(pPool, rWc, nullptr, pGk, CD, CD, CD, CD,
        0,0,0,0,0,0,1, nullptr, nullptr, nullptr, nullptr);

    // gate / nu hidden layers on tensor cores (output into g_S scratch)
    tc_gemm<0,0><<<dim3(CHGATE/128, CM/128, 1), 256, SMEM>>>(pPool, rG1, rg_b1, pHg,
        CD, CD, CD, CHGATE, 0,0,0,0,0,0,1, nullptr, nullptr, nullptr, nullptr);
    tc_gemm<0,0><<<dim3(CHNU/128, CM/128, 1), 256, SMEM>>>(pPool, rN1, nu_b1, pHn,
        CD, CD, CD, CHNU, 0,0,0,0,0,0,1, nullptr, nullptr, nullptr, nullptr);
    gate2_kernel<<<CM/8, 256>>>(pHg, rg_w2, rg_b2);
    nu2_kernel<<<CM/8, 256>>>(pHn, nu_w2, nu_b2, nu_diff, nu_adv);

    // coherence bias: gb[b] = tanh(gamma)/32 * gk[b] @ K_raw[b]^T
    tc_gemm<2,0><<<dim3(CL/128, CL/128, CB), 256, SMEM>>>(pGk, pK, nullptr, pGb,
        CD, CD, CD, CL,
        (long)CL*CD, 0, (long)CL*CD, 0, (long)CL*CL, 0, 1,
        nullptr, nullptr, gamma, nullptr);

    rope_all_kernel<<<(CM * 512) / 256, 256>>>(z);

    tc_gemm<0,0><<<gmain, 256, SMEM>>>(pZg, rWu, bu, pU, CD, CD, CD, CD,
        0,0,0,0,0,0,1, nullptr, nullptr, nullptr, nullptr);
    tc_gemm<0,0><<<gmain, 256, SMEM>>>(pZg, rWg, bg, pG, CD, CD, CD, CD,
        0,0,0,0,0,0,1, nullptr, nullptr, nullptr, nullptr);

    // logits: S[b,h] = 0.125 * Qr_h @ Kr_h^T + gb[b], causal block skip
    tc_gemm<3,0><<<dim3(CL/128, CL/128, CB*CNH), 256, SMEM>>>(pQ, pK, nullptr, pS,
        CHD, CD, CD, CL,
        (long)CL*CD, CHD, (long)CL*CD, CHD, (long)CL*CL, (long)CL*CL, CNH,
        nullptr, nullptr, nullptr, pGb);

    smaw_kernel<<<dim3(CL, CB), 256>>>(out_aw);
    attn_pv<<<dim3(CL/128, CNH, CB), 256, SMEMP>>>();

    bilin_ln_kernel<<<CM, 256>>>(ln_w, ln_b);
    tc_gemm<1,0><<<gmain, 256, SMEM>>>(pU, rCw, Cb, out_z, CD, CD, CD, CD,
        0,0,0,0,0,0,1, z, pAo, nullptr, nullptr);
}

// round 10
// speedup vs baseline: 1.4750x; 1.4750x over previous
#include <cuda_runtime.h>
#include <math.h>
#include <stdint.h>

#define CB 2
#define CL 2048
#define CD 1024
#define CNH 16
#define CHD 64
#define CM (CB*CL)          // 4096 rows
#define CHGATE 256
#define CHNU 128

// ---------------- scratch (device globals; allocation-free rule) ----------------
__device__ float g_pool[CM*CD];
__device__ float g_Q[CM*CD];
__device__ float g_K[CM*CD];
__device__ float g_V[CM*CD];
__device__ float g_gk[CM*CD];
__device__ float g_zglu[CM*CD];
__device__ float g_U[CM*CD];
__device__ float g_Gg[CM*CD];     // GLU gate branch
__device__ float g_ao[CM*CD];     // attention output
__device__ float g_zr[CM*CD];     // tf32-rounded z
__device__ float g_Wr[7*1048576 + 393216]; // transposed+rounded weights [N,K]
__device__ float g_gb[CB*CL*CL];  // coherence bias
__device__ float g_S[134217728];  // (B,NH,L,L) logits/probs (also MLP hidden scratch)
__device__ float g_gate[CM];
__device__ float g_nu[CM];
__device__ float g_csum[CB*32*CD];// pool chunk sums
__device__ float g_ctab[3*CL*1024]; // rope tables: [base][t][cos512|sin512]
__device__ double g_invd[1536];   // inv freqs: [fast | slow | glu] x 512

// ---------------- tf32 helpers ----------------
__device__ __forceinline__ unsigned f2tf(float x) {
    unsigned r; asm("cvt.rna.tf32.f32 %0, %1;" : "=r"(r) : "f"(x)); return r;
}
__device__ __forceinline__ float tfr(float x) { return __uint_as_float(f2tf(x)); }
__device__ __forceinline__ void cpa16(float* s, const float* g) {
    unsigned sa = (unsigned)__cvta_generic_to_shared(s);
    asm volatile("cp.async.cg.shared.global [%0], [%1], 16;" :: "r"(sa), "l"(g));
}
__device__ __forceinline__ void mma8(float* d, const unsigned* a, const unsigned* b) {
    asm volatile(
        "mma.sync.aligned.m16n8k8.row.col.f32.tf32.tf32.f32 "
        "{%0,%1,%2,%3},{%4,%5,%6,%7},{%8,%9},{%0,%1,%2,%3};"
        : "+f"(d[0]), "+f"(d[1]), "+f"(d[2]), "+f"(d[3])
        : "r"(a[0]), "r"(a[1]), "r"(a[2]), "r"(a[3]), "r"(b[0]), "r"(b[1]));
}
// one x4 ldmatrix: four 8x4-float tiles -> 4 regs with (row=t/4, col=t%4) mapping
__device__ __forceinline__ void ldsm4(unsigned* r, unsigned addr) {
    asm volatile("ldmatrix.sync.aligned.m8n8.x4.shared.b16 {%0,%1,%2,%3}, [%4];"
        : "=r"(r[0]), "=r"(r[1]), "=r"(r[2]), "=r"(r[3]) : "r"(addr));
}

// ---------------- weight transpose + tf32 round: W[1024,N] -> WT[N,1024] ----------------
struct TrArgs { const float* src[9]; float* dst[9]; int N[9]; };
__global__ void wtrans_kernel(TrArgs a) {
    const int w = blockIdx.z;
    const int N = a.N[w];
    const int nx = blockIdx.x * 32;
    if (nx >= N) return;
    const int ky = blockIdx.y * 32;
    __shared__ float t[32][33];
    const float* src = a.src[w];
    const int tx = threadIdx.x, ty = threadIdx.y;   // 32 x 8
#pragma unroll
    for (int i = 0; i < 4; i++)
        t[ty + 8*i][tx] = src[(size_t)(ky + ty + 8*i) * N + nx + tx];
    __syncthreads();
    float* dst = a.dst[w];
#pragma unroll
    for (int i = 0; i < 4; i++)
        dst[(size_t)(nx + ty + 8*i) * 1024 + ky + tx] = tfr(t[tx][ty + 8*i]);
}

__global__ void round_kernel(float* __restrict__ dst, const float* __restrict__ src, int n) {
    for (int i = blockIdx.x * blockDim.x + threadIdx.x; i < n; i += gridDim.x * blockDim.x)
        dst[i] = tfr(src[i]);
}

// ---------------- tensor-core GEMM: 128x128x32 tiles, tf32, full-LDSM ----------------
// C = A[M,K] @ B[N,K]^T   (both operands K-major)
// MODE 0: C = acc + bias(optional); RND: round output to tf32
// MODE 1: C = r1 + 0.42*r2 + 1.07*(acc + bias)
// MODE 2: C = tanh(gamma)/32 * acc
// MODE 3: C = 0.125*acc + gb[l,m], causal blockskip
template<int MODE, int RND>
__global__ __launch_bounds__(256, 2) void tc_gemm(
    const float* __restrict__ A, const float* __restrict__ Bm,
    const float* __restrict__ bias, float* __restrict__ C,
    int K, int lda, int ldb, int ldc,
    long sAo, long sAi, long sBo, long sBi, long sCz, long sGo, int zdiv,
    const float* __restrict__ r1, const float* __restrict__ r2,
    const float* __restrict__ gamma, const float* __restrict__ gbb)
{
    const int bm = blockIdx.y * 128, bn = blockIdx.x * 128;
    if (MODE == 3 && bn >= bm + 128) return;
    const int z = blockIdx.z;
    const int zo = z / zdiv, zi = z - zo * zdiv;
    A  += (size_t)zo * sAo + (size_t)zi * sAi;
    Bm += (size_t)zo * sBo + (size_t)zi * sBi;
    C  += (size_t)z * sCz;
    const float* gbp = (MODE == 3) ? (gbb + (size_t)zo * sGo) : nullptr;

    extern __shared__ float sm[];
    const int STG = 9216;
    float* Asm[2] = { sm, sm + STG };
    float* Bsm[2] = { sm + 4608, sm + STG + 4608 };

    const int t = threadIdx.x;
    const int wid = t >> 5, lane = t & 31;
    const int wm = (wid >> 2) * 64, wn = (wid & 3) * 32;
    const int g = lane >> 2, tig = lane & 3;

    // LDSM per-lane byte offsets (stride-36 float rows)
    const unsigned aoff = ((lane & 15) * 36 + (lane >> 4) * 4) * 4;
    const unsigned boff = ((lane & 7) * 36 + ((lane >> 3) & 1) * 4 + (lane >> 4) * (8 * 36)) * 4;

    float acc[4][4][4];
#pragma unroll
    for (int i = 0; i < 4; i++)
#pragma unroll
        for (int j = 0; j < 4; j++)
#pragma unroll
            for (int q = 0; q < 4; q++) acc[i][j][q] = 0.f;

    auto loadT = [&](float* s, const float* G, int ld, int base, int k0) {
        int r = t >> 3, k4 = (t & 7) * 4;
#pragma unroll
        for (int it = 0; it < 4; it++)
            cpa16(s + (r + it*32)*36 + k4,
                  G + (size_t)(base + r + it*32) * ld + k0 + k4);
    };

    const int NT = K >> 5;
    loadT(Asm[0], A, lda, bm, 0);
    loadT(Bsm[0], Bm, ldb, bn, 0);
    asm volatile("cp.async.commit_group;");

    for (int kt = 0; kt < NT; kt++) {
        if (kt + 1 < NT) {
            loadT(Asm[(kt+1)&1], A, lda, bm, (kt+1)*32);
            loadT(Bsm[(kt+1)&1], Bm, ldb, bn, (kt+1)*32);
            asm volatile("cp.async.commit_group;");
            asm volatile("cp.async.wait_group 1;");
        } else {
            asm volatile("cp.async.wait_group 0;");
        }
        __syncthreads();
        const unsigned Au = (unsigned)__cvta_generic_to_shared(Asm[kt&1]);
        const unsigned Bu = (unsigned)__cvta_generic_to_shared(Bsm[kt&1]);
#pragma unroll
        for (int ks = 0; ks < 4; ks++) {
            const int k = ks * 8;
            unsigned af[4][4];
#pragma unroll
            for (int i = 0; i < 4; i++)
                ldsm4(af[i], Au + ((wm + 16*i) * 36 + k) * 4 + aoff);
            unsigned bf[4][2];
#pragma unroll
            for (int jj = 0; jj < 2; jj++) {
                unsigned r4[4];
                ldsm4(r4, Bu + ((wn + 16*jj) * 36 + k) * 4 + boff);
                bf[2*jj][0]   = r4[0];
                bf[2*jj][1]   = r4[1];
                bf[2*jj+1][0] = r4[2];
                bf[2*jj+1][1] = r4[3];
            }
#pragma unroll
            for (int i = 0; i < 4; i++)
#pragma unroll
                for (int j = 0; j < 4; j++)
                    mma8(acc[i][j], af[i], bf[j]);
        }
        __syncthreads();
    }

    float scale = 1.f;
    if (MODE == 2) scale = tanhf(gamma[0]) * 0.03125f;
    if (MODE == 3) scale = 0.125f;
#pragma unroll
    for (int i = 0; i < 4; i++) {
        const int r0 = bm + wm + 16*i + g;
#pragma unroll
        for (int j = 0; j < 4; j++) {
            const int c0 = bn + wn + 8*j + 2*tig;
#pragma unroll
            for (int h2 = 0; h2 < 2; h2++) {
                const int rr = r0 + h2*8;
                float v0 = acc[i][j][h2*2], v1 = acc[i][j][h2*2+1];
                const size_t off = (size_t)rr * ldc + c0;
                if (MODE == 0) {
                    if (bias) { v0 += bias[c0]; v1 += bias[c0+1]; }
                    if (RND) { v0 = tfr(v0); v1 = tfr(v1); }
                    C[off] = v0; C[off+1] = v1;
                } else if (MODE == 1) {
                    C[off]   = r1[off]   + 0.42f*r2[off]   + 1.07f*(v0 + bias[c0]);
                    C[off+1] = r1[off+1] + 0.42f*r2[off+1] + 1.07f*(v1 + bias[c0+1]);
                } else if (MODE == 2) {
                    C[off] = tfr(v0*scale); C[off+1] = tfr(v1*scale);
                } else {
                    const size_t go = (size_t)rr * CL + c0;
                    C[off]   = v0*scale + gbp[go];
                    C[off+1] = v1*scale + gbp[go+1];
                }
            }
        }
    }
}

// ---------------- attn_out = P @ V on tensor cores (per head, causal) ----------------
__global__ __launch_bounds__(256, 2) void attn_pv() {
    const int l0 = blockIdx.x * 128;
    const int h = blockIdx.y, b = blockIdx.z;
    const float* S = g_S + ((size_t)(b * CNH + h)) * CL * CL;
    const float* V = g_V + (size_t)b * CL * CD + h * CHD;
    float* O = g_ao + (size_t)b * CL * CD + h * CHD;

    extern __shared__ float sm[];
    const int STG = 4608 + 2304;
    float* Ssm[2] = { sm, sm + STG };
    float* Vsm[2] = { sm + 4608, sm + STG + 4608 };

    const int t = threadIdx.x;
    const int wid = t >> 5, lane = t & 31;
    const int wm = wid * 16;
    const int g = lane >> 2, tig = lane & 3;
    const unsigned aoff = ((lane & 15) * 36 + (lane >> 4) * 4) * 4;

    float acc[8][4];
#pragma unroll
    for (int j = 0; j < 8; j++)
#pragma unroll
        for (int q = 0; q < 4; q++) acc[j][q] = 0.f;

    auto loadS = [&](float* s, int k0) {
        int r = t >> 3, k4 = (t & 7) * 4;
#pragma unroll
        for (int it = 0; it < 4; it++)
            cpa16(s + (r + it*32)*36 + k4,
                  S + (size_t)(l0 + r + it*32) * CL + k0 + k4);
    };
    auto loadV = [&](float* s, int k0) {
        int kr = t >> 4, n4 = (t & 15) * 4;
#pragma unroll
        for (int it = 0; it < 2; it++)
            cpa16(s + (kr + it*16)*72 + n4,
                  V + (size_t)(k0 + kr + it*16) * CD + n4);
    };

    const int NT = (l0 + 128) >> 5;
    loadS(Ssm[0], 0); loadV(Vsm[0], 0);
    asm volatile("cp.async.commit_group;");

    for (int kt = 0; kt < NT; kt++) {
        if (kt + 1 < NT) {
            loadS(Ssm[(kt+1)&1], (kt+1)*32);
            loadV(Vsm[(kt+1)&1], (kt+1)*32);
            asm volatile("cp.async.commit_group;");
            asm volatile("cp.async.wait_group 1;");
        } else {
            asm volatile("cp.async.wait_group 0;");
        }
        __syncthreads();
        const unsigned Su = (unsigned)__cvta_generic_to_shared(Ssm[kt&1]);
        const unsigned* Bb = (const unsigned*)Vsm[kt&1];
#pragma unroll
        for (int ks = 0; ks < 4; ks++) {
            const int k = ks * 8;
            unsigned af[4];
            ldsm4(af, Su + (wm * 36 + k) * 4 + aoff);
            unsigned bf[8][2];
#pragma unroll
            for (int j = 0; j < 8; j++) {
                const unsigned* bp = Bb + (k + tig)*72 + 8*j + g;
                bf[j][0] = bp[0];
                bf[j][1] = bp[4*72];
            }
#pragma unroll
            for (int j = 0; j < 8; j++)
                mma8(acc[j], af, bf[j]);
        }
        __syncthreads();
    }
#pragma unroll
    for (int j = 0; j < 8; j++) {
        const int c0 = 8*j + 2*tig;
#pragma unroll
        for (int h2 = 0; h2 < 2; h2++) {
            const int rr = l0 + wm + g + h2*8;
            O[(size_t)rr * CD + c0]     = acc[j][h2*2];
            O[(size_t)rr * CD + c0 + 1] = acc[j][h2*2 + 1];
        }
    }
}

// ---------------- rope helpers ----------------
__global__ void inv_kernel() {
    int d = threadIdx.x;
    double e = (double)(2 * d) / (double)CD;
    g_invd[d]        = pow(1.6180339887498948482, -e);
    g_invd[512 + d]  = pow(1618.0, -e);
    g_invd[1024 + d] = pow(16180.0, -e);
}

__device__ __forceinline__ void rope_cs(double inv, int t, float* c, float* s) {
    double ang = (double)t * inv;
    double k = floor(ang * 0.15915494309189533576888376337251436);
    float a = (float)(ang - k * 6.28318530717958647692528676655900577);
    sincosf(a, s, c);
}

// rope tables: one DP evaluation per (base,t,d); layout [base][t][cos512|sin512]
__global__ void ctab_kernel() {
    int idx = blockIdx.x * blockDim.x + threadIdx.x;   // 3*2048*512
    int d = idx & 511;
    int t = (idx >> 9) & (CL - 1);
    int base = idx >> 20;
    float c, s;
    rope_cs(g_invd[base * 512 + d], t, &c, &s);
    float* o = g_ctab + (size_t)base * CL * 1024 + t * 1024;
    o[d] = c;
    o[d + 512] = s;
}

// ---------------- causal cumulative mean: 3-phase parallel scan ----------------
__global__ void poolA_kernel(const float* __restrict__ z) {
    const int c = blockIdx.x, b = blockIdx.y;
    const int t = threadIdx.x;
    const float4* zp = (const float4*)(z + ((size_t)b * CL + c * 64) * CD);
    float4* pp = (float4*)(g_pool + ((size_t)b * CL + c * 64) * CD);
    float4 acc = make_float4(0.f, 0.f, 0.f, 0.f);
    for (int r = 0; r < 64; r++) {
        float4 v = zp[r * 256 + t];
        acc.x += v.x; acc.y += v.y; acc.z += v.z; acc.w += v.w;
        pp[r * 256 + t] = acc;
    }
    ((float4*)g_csum)[((size_t)b * 32 + c) * 256 + t] = acc;
}
__global__ void poolB_kernel() {
    int idx = blockIdx.x * 256 + threadIdx.x;
    int b = idx >> 10, d = idx & 1023;
    float run = 0.f;
    for (int c = 0; c < 32; c++) {
        size_t o = ((size_t)b * 32 + c) * CD + d;
        float v = g_csum[o];
        g_csum[o] = run;
        run += v;
    }
}
__global__ void poolC_kernel() {
    size_t idx = (size_t)blockIdx.x * 256 + threadIdx.x;
    int row = (int)(idx >> 8);
    int f4 = (int)(idx & 255);
    int b = row >> 11, l = row & (CL - 1), c = l >> 6;
    float4 off = ((const float4*)g_csum)[((size_t)(b * 32 + c)) * 256 + f4];
    float4 v = ((float4*)g_pool)[idx];
    float inv = 1.f / (float)(l + 1);
    v.x = tfr((v.x + off.x) * inv);
    v.y = tfr((v.y + off.y) * inv);
    v.z = tfr((v.z + off.z) * inv);
    v.w = tfr((v.w + off.w) * inv);
    ((float4*)g_pool)[idx] = v;
}

// ---------------- gate/nu epilogues ----------------
__global__ __launch_bounds__(256) void gate2_kernel(
    const float* __restrict__ hid, const float* __restrict__ w2,
    const float* __restrict__ b2)
{
    int row = blockIdx.x * 8 + (threadIdx.x >> 5);
    int lane = threadIdx.x & 31;
    const float* hr = hid + (size_t)row * CHGATE;
    float acc = 0.f;
#pragma unroll
    for (int j = 0; j < 8; j++) {
        int c = lane + j * 32;
        float x = hr[c];
        float h = 0.5f * x * (1.f + erff(x * 0.7071067811865476f));
        acc += h * w2[c];
    }
#pragma unroll
    for (int o = 16; o > 0; o >>= 1) acc += __shfl_xor_sync(~0u, acc, o);
    if (lane == 0) {
        float y = acc + b2[0];
        g_gate[row] = 1.f / (1.f + expf(-y));
    }
}
__global__ __launch_bounds__(256) void nu2_kernel(
    const float* __restrict__ hid, const float* __restrict__ w2,
    const float* __restrict__ b2,
    const float* __restrict__ nu_diff, const float* __restrict__ nu_adv)
{
    int row = blockIdx.x * 8 + (threadIdx.x >> 5);
    int lane = threadIdx.x & 31;
    const float* hr = hid + (size_t)row * CHNU;
    float acc = 0.f;
#pragma unroll
    for (int j = 0; j < 4; j++) {
        int c = lane + j * 32;
        acc += tanhf(hr[c]) * w2[c];
    }
#pragma unroll
    for (int o = 16; o > 0; o >>= 1) acc += __shfl_xor_sync(~0u, acc, o);
    if (lane == 0) {
        g_nu[row] = fabsf(nu_diff[0]) + tanhf(acc + b2[0]) * fabsf(nu_adv[0]);
    }
}

// ---------------- merged RoPE from tables: Q/K in-place + zglu write ----------------
__global__ void rope_all_kernel(const float* __restrict__ z) {
    int idx = blockIdx.x * blockDim.x + threadIdx.x;
    if (idx >= CM * 512) return;
    int d = idx & 511;
    int row = idx >> 9;
    int t = row & (CL - 1);
    float g = g_gate[row];
    const float* tf = g_ctab + (size_t)t * 1024 + d;
    const float* ts = tf + (size_t)CL * 1024;
    const float* tg = ts + (size_t)CL * 1024;
    float c = g * tf[0] + (1.f - g) * ts[0];
    float s = g * tf[512] + (1.f - g) * ts[512];
    float cg = tg[0], sg = tg[512];
    size_t lo = (size_t)row * CD + d, hi = lo + 512;
    float ql = g_Q[lo], qh = g_Q[hi];
    g_Q[lo] = tfr(ql * c - qh * s);
    g_Q[hi] = tfr(qh * c + ql * s);
    float kl = g_K[lo], kh = g_K[hi];
    g_K[lo] = tfr(kl * c - kh * s);
    g_K[hi] = tfr(kh * c + kl * s);
    float xl = z[lo], xh = z[hi];
    g_zglu[lo] = tfr(xl * cg - xh * sg);
    g_zglu[hi] = tfr(xh * cg + xl * sg);
}

// ---------------- fused causal softmax (16 heads serial) + head-mean, float4 ----------------
__global__ __launch_bounds__(256) void smaw_kernel(float* __restrict__ aw) {
    const int l = blockIdx.x;
    const int b = blockIdx.y;
    const int n = l + 1;
    const int bound = ((l >> 7) + 1) << 7;     // 128-block boundary for attn_pv
    const int tid = threadIdx.x;
    const int lane = tid & 31, wid = tid >> 5;
    __shared__ float red[8];
    float4 awacc[2];
    awacc[0] = make_float4(0.f, 0.f, 0.f, 0.f);
    awacc[1] = make_float4(0.f, 0.f, 0.f, 0.f);
    const float NEG = -3.4e38f;

    for (int h = 0; h < CNH; h++) {
        float* row = g_S + ((size_t)(b * CNH + h) * CL + l) * CL;
        float4* row4 = (float4*)row;
        float4 v[2];
        float mx = NEG;
#pragma unroll
        for (int ii = 0; ii < 2; ii++) {
            int f4 = tid + ii * 256;
            int c0 = f4 * 4;
            if (c0 < n) {
                float4 tv = row4[f4];
                if (c0 + 1 >= n) tv.y = NEG;
                if (c0 + 2 >= n) tv.z = NEG;
                if (c0 + 3 >= n) tv.w = NEG;
                v[ii] = tv;
            } else {
                v[ii] = make_float4(NEG, NEG, NEG, NEG);
            }
            mx = fmaxf(mx, fmaxf(fmaxf(v[ii].x, v[ii].y), fmaxf(v[ii].z, v[ii].w)));
        }
#pragma unroll
        for (int o = 16; o > 0; o >>= 1) mx = fmaxf(mx, __shfl_xor_sync(~0u, mx, o));
        if (lane == 0) red[wid] = mx;
        __syncthreads();
        mx = red[0];
#pragma unroll
        for (int w = 1; w < 8; w++) mx = fmaxf(mx, red[w]);
        __syncthreads();

        float sum = 0.f;
#pragma unroll
        for (int ii = 0; ii < 2; ii++) {
            v[ii].x = expf(v[ii].x - mx);
            v[ii].y = expf(v[ii].y - mx);
            v[ii].z = expf(v[ii].z - mx);
            v[ii].w = expf(v[ii].w - mx);
            sum += v[ii].x + v[ii].y + v[ii].z + v[ii].w;
        }
#pragma unroll
        for (int o = 16; o > 0; o >>= 1) sum += __shfl_xor_sync(~0u, sum, o);
        if (lane == 0) red[wid] = sum;
        __syncthreads();
        sum = red[0];
#pragma unroll
        for (int w = 1; w < 8; w++) sum += red[w];
        __syncthreads();
        float rinv = 1.f / sum;

#pragma unroll
        for (int ii = 0; ii < 2; ii++) {
            int f4 = tid + ii * 256;
            int c0 = f4 * 4;
            if (c0 < bound) {
                float4 p;
                p.x = v[ii].x * rinv; p.y = v[ii].y * rinv;
                p.z = v[ii].z * rinv; p.w = v[ii].w * rinv;
                awacc[ii].x += p.x; awacc[ii].y += p.y;
                awacc[ii].z += p.z; awacc[ii].w += p.w;
                float4 pr;
                pr.x = tfr(p.x); pr.y = tfr(p.y); pr.z = tfr(p.z); pr.w = tfr(p.w);
                row4[f4] = pr;
            }
        }
    }
    float4* awr4 = (float4*)(aw + ((size_t)b * CL + l) * CL);
    const float s16 = 1.f / CNH;
#pragma unroll
    for (int ii = 0; ii < 2; ii++) {
        int f4 = tid + ii * 256;
        float4 o;
        o.x = awacc[ii].x * s16; o.y = awacc[ii].y * s16;
        o.z = awacc[ii].z * s16; o.w = awacc[ii].w * s16;
        awr4[f4] = o;
    }
}

// ---------------- bilinear * (-nu) + LayerNorm (rounded out) ----------------
__global__ __launch_bounds__(256) void bilin_ln_kernel(
    const float* __restrict__ ln_w, const float* __restrict__ ln_b)
{
    int row = blockIdx.x;
    int tid = threadIdx.x;
    size_t off = (size_t)row * CD;
    float nu = g_nu[row];
    __shared__ float red[256], red2[256];
    float a[4]; float s = 0.f, s2 = 0.f;
#pragma unroll
    for (int i = 0; i < 4; i++) {
        int d = tid + i * 256;
        float v = -nu * g_U[off + d] * g_Gg[off + d];
        a[i] = v; s += v; s2 += v * v;
    }
    red[tid] = s; red2[tid] = s2; __syncthreads();
    for (int st = 128; st > 0; st >>= 1) {
        if (tid < st) { red[tid] += red[tid + st]; red2[tid] += red2[tid + st]; }
        __syncthreads();
    }
    float mu = red[0] * (1.f / CD);
    float var = red2[0] * (1.f / CD) - mu * mu;
    float rstd = rsqrtf(var + 1e-5f);
#pragma unroll
    for (int i = 0; i < 4; i++) {
        int d = tid + i * 256;
        g_U[off + d] = tfr((a[i] - mu) * rstd * ln_w[d] + ln_b[d]);
    }
}

// ---------------- launcher ----------------
extern "C" void kernel_launch(void* const* d_in, const int* in_sizes, int n_in,
                              void* d_out, int out_size) {
    (void)in_sizes; (void)n_in; (void)out_size;
    const float* z     = (const float*)d_in[0];
    const float* Wq    = (const float*)d_in[1];
    const float* bq    = (const float*)d_in[2];
    const float* Wk    = (const float*)d_in[3];
    const float* bk    = (const float*)d_in[4];
    const float* Wv    = (const float*)d_in[5];
    const float* bv    = (const float*)d_in[6];
    const float* Wcoh  = (const float*)d_in[7];
    const float* gamma = (const float*)d_in[8];
    const float* rg_w1 = (const float*)d_in[9];
    const float* rg_b1 = (const float*)d_in[10];
    const float* rg_w2 = (const float*)d_in[11];
    const float* rg_b2 = (const float*)d_in[12];
    const float* nu_diff = (const float*)d_in[13];
    const float* nu_adv  = (const float*)d_in[14];
    const float* nu_w1 = (const float*)d_in[15];
    const float* nu_b1 = (const float*)d_in[16];
    const float* nu_w2 = (const float*)d_in[17];
    const float* nu_b2 = (const float*)d_in[18];
    const float* Wu    = (const float*)d_in[19];
    const float* bu    = (const float*)d_in[20];
    const float* Wg    = (const float*)d_in[21];
    const float* bg    = (const float*)d_in[22];
    const float* ln_w  = (const float*)d_in[23];
    const float* ln_b  = (const float*)d_in[24];
    const float* Cw    = (const float*)d_in[25];
    const float* Cb    = (const float*)d_in[26];

    float* out_z  = (float*)d_out;
    float* out_aw = out_z + (size_t)CM * CD;

    void* tmp;
    cudaGetSymbolAddress(&tmp, g_pool); float* pPool = (float*)tmp;
    cudaGetSymbolAddress(&tmp, g_Q);    float* pQ    = (float*)tmp;
    cudaGetSymbolAddress(&tmp, g_K);    float* pK    = (float*)tmp;
    cudaGetSymbolAddress(&tmp, g_V);    float* pV    = (float*)tmp;
    cudaGetSymbolAddress(&tmp, g_gk);   float* pGk   = (float*)tmp;
    cudaGetSymbolAddress(&tmp, g_zglu); float* pZg   = (float*)tmp;
    cudaGetSymbolAddress(&tmp, g_U);    float* pU    = (float*)tmp;
    cudaGetSymbolAddress(&tmp, g_Gg);   float* pG    = (float*)tmp;
    cudaGetSymbolAddress(&tmp, g_ao);   float* pAo   = (float*)tmp;
    cudaGetSymbolAddress(&tmp, g_zr);   float* pZr   = (float*)tmp;
    cudaGetSymbolAddress(&tmp, g_Wr);   float* pWr   = (float*)tmp;
    cudaGetSymbolAddress(&tmp, g_gb);   float* pGb   = (float*)tmp;
    cudaGetSymbolAddress(&tmp, g_S);    float* pS    = (float*)tmp;

    float* rWq = pWr;                         // all transposed [N,K=1024]
    float* rWk = pWr + 1048576;
    float* rWv = pWr + 2*1048576;
    float* rWc = pWr + 3*1048576;
    float* rWu = pWr + 4*1048576;
    float* rWg = pWr + 5*1048576;
    float* rCw = pWr + 6*1048576;
    float* rG1 = pWr + 7*1048576;             // rg_w1^T (256 x 1024)
    float* rN1 = pWr + 7*1048576 + 262144;    // nu_w1^T (128 x 1024)

    float* pHg = pS;                          // gate hidden (CM x 256) in g_S scratch
    float* pHn = pS + (size_t)CM * CHGATE;    // nu hidden   (CM x 128)

    const size_t SMEM  = 2 * 9216 * sizeof(float);   // 73728
    const size_t SMEMP = 2 * 6912 * sizeof(float);   // 55296 (attn_pv)
    cudaFuncSetAttribute(tc_gemm<0,0>, cudaFuncAttributeMaxDynamicSharedMemorySize, (int)SMEM);
    cudaFuncSetAttribute(tc_gemm<0,1>, cudaFuncAttributeMaxDynamicSharedMemorySize, (int)SMEM);
    cudaFuncSetAttribute(tc_gemm<1,0>, cudaFuncAttributeMaxDynamicSharedMemorySize, (int)SMEM);
    cudaFuncSetAttribute(tc_gemm<2,0>, cudaFuncAttributeMaxDynamicSharedMemorySize, (int)SMEM);
    cudaFuncSetAttribute(tc_gemm<3,0>, cudaFuncAttributeMaxDynamicSharedMemorySize, (int)SMEM);
    cudaFuncSetAttribute(attn_pv, cudaFuncAttributeMaxDynamicSharedMemorySize, (int)SMEMP);

    dim3 gmain(CD / 128, CM / 128, 1);   // (8, 32)

    inv_kernel<<<1, 512>>>();                                        // 1

    TrArgs ta;
    ta.src[0]=Wq;   ta.dst[0]=rWq; ta.N[0]=1024;
    ta.src[1]=Wk;   ta.dst[1]=rWk; ta.N[1]=1024;
    ta.src[2]=Wv;   ta.dst[2]=rWv; ta.N[2]=1024;
    ta.src[3]=Wcoh; ta.dst[3]=rWc; ta.N[3]=1024;
    ta.src[4]=Wu;   ta.dst[4]=rWu; ta.N[4]=1024;
    ta.src[5]=Wg;   ta.dst[5]=rWg; ta.N[5]=1024;
    ta.src[6]=Cw;   ta.dst[6]=rCw; ta.N[6]=1024;
    ta.src[7]=rg_w1;ta.dst[7]=rG1; ta.N[7]=256;
    ta.src[8]=nu_w1;ta.dst[8]=rN1; ta.N[8]=128;
    wtrans_kernel<<<dim3(32, 32, 9), dim3(32, 8)>>>(ta);             // 2
    round_kernel<<<2048, 256>>>(pZr, z, CM*CD);                      // 3

    // Q/K/V GEMMs early: launches 4-6 so ncu (-s 5 -c 1) captures a tc_gemm
    tc_gemm<0,0><<<gmain, 256, SMEM>>>(pZr, rWq, bq, pQ, CD, CD, CD, CD,    // 4
        0,0,0,0,0,0,1, nullptr, nullptr, nullptr, nullptr);
    tc_gemm<0,1><<<gmain, 256, SMEM>>>(pZr, rWk, bk, pK, CD, CD, CD, CD,    // 5
        0,0,0,0,0,0,1, nullptr, nullptr, nullptr, nullptr);
    tc_gemm<0,1><<<gmain, 256, SMEM>>>(pZr, rWv, bv, pV, CD, CD, CD, CD,    // 6
        0,0,0,0,0,0,1, nullptr, nullptr, nullptr, nullptr);

    poolA_kernel<<<dim3(32, CB), 256>>>(z);                          // 7
    poolB_kernel<<<8, 256>>>();                                      // 8
    poolC_kernel<<<CM, 256>>>();                                     // 9
    ctab_kernel<<<(3 * CL * 512) / 256, 256>>>();                    // 10

    tc_gemm<0,1><<<gmain, 256, SMEM>>>(pPool, rWc, nullptr, pGk, CD, CD, CD, CD,
        0,0,0,0,0,0,1, nullptr, nullptr, nullptr, nullptr);

    // gate / nu hidden layers on tensor cores (output into g_S scratch)
    tc_gemm<0,0><<<dim3(CHGATE/128, CM/128, 1), 256, SMEM>>>(pPool, rG1, rg_b1, pHg,
        CD, CD, CD, CHGATE, 0,0,0,0,0,0,1, nullptr, nullptr, nullptr, nullptr);
    tc_gemm<0,0><<<dim3(CHNU/128, CM/128, 1), 256, SMEM>>>(pPool, rN1, nu_b1, pHn,
        CD, CD, CD, CHNU, 0,0,0,0,0,0,1, nullptr, nullptr, nullptr, nullptr);
    gate2_kernel<<<CM/8, 256>>>(pHg, rg_w2, rg_b2);
    nu2_kernel<<<CM/8, 256>>>(pHn, nu_w2, nu_b2, nu_diff, nu_adv);

    // coherence bias: gb[b] = tanh(gamma)/32 * gk[b] @ K_raw[b]^T
    tc_gemm<2,0><<<dim3(CL/128, CL/128, CB), 256, SMEM>>>(pGk, pK, nullptr, pGb,
        CD, CD, CD, CL,
        (long)CL*CD, 0, (long)CL*CD, 0, (long)CL*CL, 0, 1,
        nullptr, nullptr, gamma, nullptr);

    rope_all_kernel<<<(CM * 512) / 256, 256>>>(z);

    tc_gemm<0,0><<<gmain, 256, SMEM>>>(pZg, rWu, bu, pU, CD, CD, CD, CD,
        0,0,0,0,0,0,1, nullptr, nullptr, nullptr, nullptr);
    tc_gemm<0,0><<<gmain, 256, SMEM>>>(pZg, rWg, bg, pG, CD, CD, CD, CD,
        0,0,0,0,0,0,1, nullptr, nullptr, nullptr, nullptr);

    // logits: S[b,h] = 0.125 * Qr_h @ Kr_h^T + gb[b], causal block skip
    tc_gemm<3,0><<<dim3(CL/128, CL/128, CB*CNH), 256, SMEM>>>(pQ, pK, nullptr, pS,
        CHD, CD, CD, CL,
        (long)CL*CD, CHD, (long)CL*CD, CHD, (long)CL*CL, (long)CL*CL, CNH,
        nullptr, nullptr, nullptr, pGb);

    smaw_kernel<<<dim3(CL, CB), 256>>>(out_aw);
    attn_pv<<<dim3(CL/128, CNH, CB), 256, SMEMP>>>();

    bilin_ln_kernel<<<CM, 256>>>(ln_w, ln_b);
    tc_gemm<1,0><<<gmain, 256, SMEM>>>(pU, rCw, Cb, out_z, CD, CD, CD, CD,
        0,0,0,0,0,0,1, z, pAo, nullptr, nullptr);
}

// round 11
// speedup vs baseline: 1.5861x; 1.0753x over previous
#include <cuda_runtime.h>
#include <cuda_bf16.h>
#include <math.h>
#include <stdint.h>

#define CB 2
#define CL 2048
#define CD 1024
#define CNH 16
#define CHD 64
#define CM (CB*CL)          // 4096 rows
#define CHGATE 256
#define CHNU 128

// ---------------- scratch (device globals; allocation-free rule) ----------------
__device__ float g_pool[CM*CD];
__device__ float g_QKV[3*CM*CD];  // Q | K | V
__device__ float g_UG[2*CM*CD];   // U | G (adv_n written back into U slice)
__device__ __nv_bfloat16 g_Vh[CM*CD]; // bf16 V for attn_pv
__device__ float g_gk[CM*CD];
__device__ float g_zglu[CM*CD];
__device__ float g_ao[CM*CD];     // attention output
__device__ float g_zr[CM*CD];     // tf32-rounded z
__device__ float g_Wr[7*1048576 + 393216]; // transposed+rounded weights [N,K]
__device__ float g_bcat[5*1024];  // bq|bk|bv|bu|bg
__device__ float g_gb[CB*CL*CL];  // coherence bias
__device__ float g_S[134217728];  // (B,NH,L,L) logits (fp32) -> probs (bf16 in-place)
__device__ float g_gate[CM];
__device__ float g_nu[CM];
__device__ float g_csum[CB*32*CD];// pool chunk sums
__device__ float g_ctab[3*CL*1024]; // rope tables: [base][t][cos512|sin512]
__device__ double g_invd[1536];   // inv freqs: [fast | slow | glu] x 512

// ---------------- helpers ----------------
__device__ __forceinline__ unsigned f2tf(float x) {
    unsigned r; asm("cvt.rna.tf32.f32 %0, %1;" : "=r"(r) : "f"(x)); return r;
}
__device__ __forceinline__ float tfr(float x) { return __uint_as_float(f2tf(x)); }
__device__ __forceinline__ void cpa16(float* s, const float* g) {
    unsigned sa = (unsigned)__cvta_generic_to_shared(s);
    asm volatile("cp.async.cg.shared.global [%0], [%1], 16;" :: "r"(sa), "l"(g));
}
__device__ __forceinline__ void cpa16b(void* s, const void* g) {
    unsigned sa = (unsigned)__cvta_generic_to_shared(s);
    asm volatile("cp.async.cg.shared.global [%0], [%1], 16;" :: "r"(sa), "l"(g));
}
__device__ __forceinline__ void mma8(float* d, const unsigned* a, const unsigned* b) {
    asm volatile(
        "mma.sync.aligned.m16n8k8.row.col.f32.tf32.tf32.f32 "
        "{%0,%1,%2,%3},{%4,%5,%6,%7},{%8,%9},{%0,%1,%2,%3};"
        : "+f"(d[0]), "+f"(d[1]), "+f"(d[2]), "+f"(d[3])
        : "r"(a[0]), "r"(a[1]), "r"(a[2]), "r"(a[3]), "r"(b[0]), "r"(b[1]));
}
__device__ __forceinline__ void mma16(float* d, const unsigned* a, const unsigned* b) {
    asm volatile(
        "mma.sync.aligned.m16n8k16.row.col.f32.bf16.bf16.f32 "
        "{%0,%1,%2,%3},{%4,%5,%6,%7},{%8,%9},{%0,%1,%2,%3};"
        : "+f"(d[0]), "+f"(d[1]), "+f"(d[2]), "+f"(d[3])
        : "r"(a[0]), "r"(a[1]), "r"(a[2]), "r"(a[3]), "r"(b[0]), "r"(b[1]));
}
__device__ __forceinline__ void ldsm4(unsigned* r, unsigned addr) {
    asm volatile("ldmatrix.sync.aligned.m8n8.x4.shared.b16 {%0,%1,%2,%3}, [%4];"
        : "=r"(r[0]), "=r"(r[1]), "=r"(r[2]), "=r"(r[3]) : "r"(addr));
}
__device__ __forceinline__ void ldsm4t(unsigned* r, unsigned addr) {
    asm volatile("ldmatrix.sync.aligned.m8n8.x4.trans.shared.b16 {%0,%1,%2,%3}, [%4];"
        : "=r"(r[0]), "=r"(r[1]), "=r"(r[2]), "=r"(r[3]) : "r"(addr));
}
__device__ __forceinline__ unsigned pack_bf(float a, float b) {
    __nv_bfloat162 h = __floats2bfloat162_rn(a, b);   // .x=a (low), .y=b (high)
    return *(unsigned*)&h;
}

// ---------------- weight transpose + tf32 round (+ bias concat at z=9) ----------------
struct TrArgs { const float* src[9]; float* dst[9]; int N[9]; const float* bsrc[5]; float* bdst; };
__global__ void wtrans_kernel(TrArgs a) {
    const int w = blockIdx.z;
    if (w == 9) {
        int i = blockIdx.x;
        if (i < 5 && blockIdx.y == 0) {
            int t = threadIdx.y * 32 + threadIdx.x;   // 0..255
#pragma unroll
            for (int j = 0; j < 4; j++)
                a.bdst[i * 1024 + t + j * 256] = a.bsrc[i][t + j * 256];
        }
        return;
    }
    const int N = a.N[w];
    const int nx = blockIdx.x * 32;
    if (nx >= N) return;
    const int ky = blockIdx.y * 32;
    __shared__ float t[32][33];
    const float* src = a.src[w];
    const int tx = threadIdx.x, ty = threadIdx.y;   // 32 x 8
#pragma unroll
    for (int i = 0; i < 4; i++)
        t[ty + 8*i][tx] = src[(size_t)(ky + ty + 8*i) * N + nx + tx];
    __syncthreads();
    float* dst = a.dst[w];
#pragma unroll
    for (int i = 0; i < 4; i++)
        dst[(size_t)(nx + ty + 8*i) * 1024 + ky + tx] = tfr(t[tx][ty + 8*i]);
}

__global__ void round_kernel(float* __restrict__ dst, const float* __restrict__ src, int n) {
    for (int i = blockIdx.x * blockDim.x + threadIdx.x; i < n; i += gridDim.x * blockDim.x)
        dst[i] = tfr(src[i]);
}

__global__ void cvtV_kernel(const float* __restrict__ v, __nv_bfloat16* __restrict__ o) {
    int i = blockIdx.x * 256 + threadIdx.x;           // over CM*CD/4
    float4 x = ((const float4*)v)[i];
    uint2 u;
    u.x = pack_bf(x.x, x.y);
    u.y = pack_bf(x.z, x.w);
    ((uint2*)o)[i] = u;
}

// ---------------- tensor-core GEMM: 128x128x32 tiles, tf32, full-LDSM ----------------
// C = A[M,K] @ B[N,K]^T   (both operands K-major)
// MODE 0: C = acc + bias(optional, +z*sBz); RND rounds output to tf32
// MODE 1: C = r1 + 0.42*r2 + 1.07*(acc + bias)
// MODE 2: C = tanh(gamma)/32 * acc
// MODE 3: C = 0.125*acc + gb[l,m], causal blockskip
template<int MODE, int RND>
__global__ __launch_bounds__(256, 2) void tc_gemm(
    const float* __restrict__ A, const float* __restrict__ Bm,
    const float* __restrict__ bias, float* __restrict__ C,
    int K, int lda, int ldb, int ldc,
    long sAo, long sAi, long sBo, long sBi, long sCz, long sGo, long sBz, int zdiv,
    const float* __restrict__ r1, const float* __restrict__ r2,
    const float* __restrict__ gamma, const float* __restrict__ gbb)
{
    const int bm = blockIdx.y * 128, bn = blockIdx.x * 128;
    if (MODE == 3 && bn >= bm + 128) return;
    const int z = blockIdx.z;
    const int zo = z / zdiv, zi = z - zo * zdiv;
    A  += (size_t)zo * sAo + (size_t)zi * sAi;
    Bm += (size_t)zo * sBo + (size_t)zi * sBi;
    C  += (size_t)z * sCz;
    if (bias) bias += (size_t)z * sBz;
    const float* gbp = (MODE == 3) ? (gbb + (size_t)zo * sGo) : nullptr;

    extern __shared__ float sm[];
    const int STG = 9216;
    float* Asm[2] = { sm, sm + STG };
    float* Bsm[2] = { sm + 4608, sm + STG + 4608 };

    const int t = threadIdx.x;
    const int wid = t >> 5, lane = t & 31;
    const int wm = (wid >> 2) * 64, wn = (wid & 3) * 32;
    const int g = lane >> 2, tig = lane & 3;

    const unsigned aoff = ((lane & 15) * 36 + (lane >> 4) * 4) * 4;
    const unsigned boff = ((lane & 7) * 36 + ((lane >> 3) & 1) * 4 + (lane >> 4) * (8 * 36)) * 4;

    float acc[4][4][4];
#pragma unroll
    for (int i = 0; i < 4; i++)
#pragma unroll
        for (int j = 0; j < 4; j++)
#pragma unroll
            for (int q = 0; q < 4; q++) acc[i][j][q] = 0.f;

    auto loadT = [&](float* s, const float* G, int ld, int base, int k0) {
        int r = t >> 3, k4 = (t & 7) * 4;
#pragma unroll
        for (int it = 0; it < 4; it++)
            cpa16(s + (r + it*32)*36 + k4,
                  G + (size_t)(base + r + it*32) * ld + k0 + k4);
    };

    const int NT = K >> 5;
    loadT(Asm[0], A, lda, bm, 0);
    loadT(Bsm[0], Bm, ldb, bn, 0);
    asm volatile("cp.async.commit_group;");

    for (int kt = 0; kt < NT; kt++) {
        if (kt + 1 < NT) {
            loadT(Asm[(kt+1)&1], A, lda, bm, (kt+1)*32);
            loadT(Bsm[(kt+1)&1], Bm, ldb, bn, (kt+1)*32);
            asm volatile("cp.async.commit_group;");
            asm volatile("cp.async.wait_group 1;");
        } else {
            asm volatile("cp.async.wait_group 0;");
        }
        __syncthreads();
        const unsigned Au = (unsigned)__cvta_generic_to_shared(Asm[kt&1]);
        const unsigned Bu = (unsigned)__cvta_generic_to_shared(Bsm[kt&1]);
#pragma unroll
        for (int ks = 0; ks < 4; ks++) {
            const int k = ks * 8;
            unsigned af[4][4];
#pragma unroll
            for (int i = 0; i < 4; i++)
                ldsm4(af[i], Au + ((wm + 16*i) * 36 + k) * 4 + aoff);
            unsigned bf[4][2];
#pragma unroll
            for (int jj = 0; jj < 2; jj++) {
                unsigned r4[4];
                ldsm4(r4, Bu + ((wn + 16*jj) * 36 + k) * 4 + boff);
                bf[2*jj][0]   = r4[0];
                bf[2*jj][1]   = r4[1];
                bf[2*jj+1][0] = r4[2];
                bf[2*jj+1][1] = r4[3];
            }
#pragma unroll
            for (int i = 0; i < 4; i++)
#pragma unroll
                for (int j = 0; j < 4; j++)
                    mma8(acc[i][j], af[i], bf[j]);
        }
        __syncthreads();
    }

    float scale = 1.f;
    if (MODE == 2) scale = tanhf(gamma[0]) * 0.03125f;
    if (MODE == 3) scale = 0.125f;
#pragma unroll
    for (int i = 0; i < 4; i++) {
        const int r0 = bm + wm + 16*i + g;
#pragma unroll
        for (int j = 0; j < 4; j++) {
            const int c0 = bn + wn + 8*j + 2*tig;
#pragma unroll
            for (int h2 = 0; h2 < 2; h2++) {
                const int rr = r0 + h2*8;
                float v0 = acc[i][j][h2*2], v1 = acc[i][j][h2*2+1];
                const size_t off = (size_t)rr * ldc + c0;
                if (MODE == 0) {
                    if (bias) { v0 += bias[c0]; v1 += bias[c0+1]; }
                    if (RND) { v0 = tfr(v0); v1 = tfr(v1); }
                    C[off] = v0; C[off+1] = v1;
                } else if (MODE == 1) {
                    C[off]   = r1[off]   + 0.42f*r2[off]   + 1.07f*(v0 + bias[c0]);
                    C[off+1] = r1[off+1] + 0.42f*r2[off+1] + 1.07f*(v1 + bias[c0+1]);
                } else if (MODE == 2) {
                    C[off] = tfr(v0*scale); C[off+1] = tfr(v1*scale);
                } else {
                    const size_t go = (size_t)rr * CL + c0;
                    C[off]   = v0*scale + gbp[go];
                    C[off+1] = v1*scale + gbp[go+1];
                }
            }
        }
    }
}

// ---------------- attn_out = P(bf16) @ V(bf16), m16n8k16 MMA, causal ----------------
__global__ __launch_bounds__(256) void attn_pv(const __nv_bfloat16* __restrict__ Vh) {
    const int l0 = blockIdx.x * 128;
    const int h = blockIdx.y, b = blockIdx.z;
    // bf16 probs live in-place at the base of each fp32 logit row
    const char* Sb = (const char*)g_S + (((size_t)(b * CNH + h) * CL + l0) * CL) * 4;
    const __nv_bfloat16* V = Vh + (size_t)b * CL * CD + h * CHD;
    float* O = g_ao + (size_t)b * CL * CD + h * CHD;

    extern __shared__ char smc[];
    const int STG = 14848;                    // S 128*80 + V 32*144
    char* Ss[2] = { smc, smc + STG };
    char* Vs[2] = { smc + 10240, smc + STG + 10240 };

    const int t = threadIdx.x;
    const int wid = t >> 5, lane = t & 31;
    const int wm = wid * 16;
    const int g = lane >> 2, tig = lane & 3;
    const int mrow = ((lane >> 3) & 1) * 8 + (lane & 7);   // ldsm matrix row
    const int mcb  = ((lane >> 4) & 1) * 16;               // 8 bf16 = 16B col sel

    float acc[8][4];
#pragma unroll
    for (int j = 0; j < 8; j++)
#pragma unroll
        for (int q = 0; q < 4; q++) acc[j][q] = 0.f;

    auto loadS = [&](char* s, int k0) {
#pragma unroll
        for (int j = 0; j < 2; j++) {
            int a = t * 2 + j;                // 512 chunks: 128 rows x 4x16B
            int row = a >> 2, ch = a & 3;
            cpa16b(s + row * 80 + ch * 16,
                   Sb + (size_t)row * CL * 4 + k0 * 2 + ch * 16);
        }
    };
    auto loadV = [&](char* s, int k0) {
        int row = t >> 3, ch = t & 7;         // 32 rows x 8x16B
        cpa16b(s + row * 144 + ch * 16,
               (const char*)(V + (size_t)(k0 + row) * CD) + ch * 16);
    };

    const int NT = (l0 + 128) >> 5;
    loadS(Ss[0], 0); loadV(Vs[0], 0);
    asm volatile("cp.async.commit_group;");

    for (int kt = 0; kt < NT; kt++) {
        if (kt + 1 < NT) {
            loadS(Ss[(kt+1)&1], (kt+1)*32);
            loadV(Vs[(kt+1)&1], (kt+1)*32);
            asm volatile("cp.async.commit_group;");
            asm volatile("cp.async.wait_group 1;");
        } else {
            asm volatile("cp.async.wait_group 0;");
        }
        __syncthreads();
        const unsigned Su = (unsigned)__cvta_generic_to_shared(Ss[kt&1]);
        const unsigned Vu = (unsigned)__cvta_generic_to_shared(Vs[kt&1]);
#pragma unroll
        for (int ks = 0; ks < 2; ks++) {      // two k16 steps per 32-k tile
            unsigned af[4];
            ldsm4(af, Su + (wm + mrow) * 80 + ks * 32 + mcb);
            unsigned bf[8][2];
#pragma unroll
            for (int nt = 0; nt < 4; nt++) {
                unsigned r4[4];
                ldsm4t(r4, Vu + (ks * 16 + mrow) * 144 + nt * 32 + mcb);
                bf[2*nt][0]   = r4[0];
                bf[2*nt][1]   = r4[1];
                bf[2*nt+1][0] = r4[2];
                bf[2*nt+1][1] = r4[3];
            }
#pragma unroll
            for (int j = 0; j < 8; j++)
                mma16(acc[j], af, bf[j]);
        }
        __syncthreads();
    }
#pragma unroll
    for (int j = 0; j < 8; j++) {
        const int c0 = 8*j + 2*tig;
#pragma unroll
        for (int h2 = 0; h2 < 2; h2++) {
            const int rr = l0 + wm + g + h2*8;
            O[(size_t)rr * CD + c0]     = acc[j][h2*2];
            O[(size_t)rr * CD + c0 + 1] = acc[j][h2*2 + 1];
        }
    }
}

// ---------------- rope helpers ----------------
__global__ void inv_kernel() {
    int d = threadIdx.x;
    double e = (double)(2 * d) / (double)CD;
    g_invd[d]        = pow(1.6180339887498948482, -e);
    g_invd[512 + d]  = pow(1618.0, -e);
    g_invd[1024 + d] = pow(16180.0, -e);
}

__device__ __forceinline__ void rope_cs(double inv, int t, float* c, float* s) {
    double ang = (double)t * inv;
    double k = floor(ang * 0.15915494309189533576888376337251436);
    float a = (float)(ang - k * 6.28318530717958647692528676655900577);
    sincosf(a, s, c);
}

__global__ void ctab_kernel() {
    int idx = blockIdx.x * blockDim.x + threadIdx.x;   // 3*2048*512
    int d = idx & 511;
    int t = (idx >> 9) & (CL - 1);
    int base = idx >> 20;
    float c, s;
    rope_cs(g_invd[base * 512 + d], t, &c, &s);
    float* o = g_ctab + (size_t)base * CL * 1024 + t * 1024;
    o[d] = c;
    o[d + 512] = s;
}

// ---------------- causal cumulative mean: 3-phase parallel scan ----------------
__global__ void poolA_kernel(const float* __restrict__ z) {
    const int c = blockIdx.x, b = blockIdx.y;
    const int t = threadIdx.x;
    const float4* zp = (const float4*)(z + ((size_t)b * CL + c * 64) * CD);
    float4* pp = (float4*)(g_pool + ((size_t)b * CL + c * 64) * CD);
    float4 acc = make_float4(0.f, 0.f, 0.f, 0.f);
    for (int r = 0; r < 64; r++) {
        float4 v = zp[r * 256 + t];
        acc.x += v.x; acc.y += v.y; acc.z += v.z; acc.w += v.w;
        pp[r * 256 + t] = acc;
    }
    ((float4*)g_csum)[((size_t)b * 32 + c) * 256 + t] = acc;
}
__global__ void poolB_kernel() {
    int idx = blockIdx.x * 256 + threadIdx.x;
    int b = idx >> 10, d = idx & 1023;
    float run = 0.f;
    for (int c = 0; c < 32; c++) {
        size_t o = ((size_t)b * 32 + c) * CD + d;
        float v = g_csum[o];
        g_csum[o] = run;
        run += v;
    }
}
__global__ void poolC_kernel() {
    size_t idx = (size_t)blockIdx.x * 256 + threadIdx.x;
    int row = (int)(idx >> 8);
    int f4 = (int)(idx & 255);
    int b = row >> 11, l = row & (CL - 1), c = l >> 6;
    float4 off = ((const float4*)g_csum)[((size_t)(b * 32 + c)) * 256 + f4];
    float4 v = ((float4*)g_pool)[idx];
    float inv = 1.f / (float)(l + 1);
    v.x = tfr((v.x + off.x) * inv);
    v.y = tfr((v.y + off.y) * inv);
    v.z = tfr((v.z + off.z) * inv);
    v.w = tfr((v.w + off.w) * inv);
    ((float4*)g_pool)[idx] = v;
}

// ---------------- gate/nu epilogues ----------------
__global__ __launch_bounds__(256) void gate2_kernel(
    const float* __restrict__ hid, const float* __restrict__ w2,
    const float* __restrict__ b2)
{
    int row = blockIdx.x * 8 + (threadIdx.x >> 5);
    int lane = threadIdx.x & 31;
    const float* hr = hid + (size_t)row * CHGATE;
    float acc = 0.f;
#pragma unroll
    for (int j = 0; j < 8; j++) {
        int c = lane + j * 32;
        float x = hr[c];
        float h = 0.5f * x * (1.f + erff(x * 0.7071067811865476f));
        acc += h * w2[c];
    }
#pragma unroll
    for (int o = 16; o > 0; o >>= 1) acc += __shfl_xor_sync(~0u, acc, o);
    if (lane == 0) {
        float y = acc + b2[0];
        g_gate[row] = 1.f / (1.f + expf(-y));
    }
}
__global__ __launch_bounds__(256) void nu2_kernel(
    const float* __restrict__ hid, const float* __restrict__ w2,
    const float* __restrict__ b2,
    const float* __restrict__ nu_diff, const float* __restrict__ nu_adv)
{
    int row = blockIdx.x * 8 + (threadIdx.x >> 5);
    int lane = threadIdx.x & 31;
    const float* hr = hid + (size_t)row * CHNU;
    float acc = 0.f;
#pragma unroll
    for (int j = 0; j < 4; j++) {
        int c = lane + j * 32;
        acc += tanhf(hr[c]) * w2[c];
    }
#pragma unroll
    for (int o = 16; o > 0; o >>= 1) acc += __shfl_xor_sync(~0u, acc, o);
    if (lane == 0) {
        g_nu[row] = fabsf(nu_diff[0]) + tanhf(acc + b2[0]) * fabsf(nu_adv[0]);
    }
}

// ---------------- merged RoPE from tables: Q/K in-place + zglu write ----------------
__global__ void rope_all_kernel(const float* __restrict__ z,
                                float* __restrict__ Q, float* __restrict__ K) {
    int idx = blockIdx.x * blockDim.x + threadIdx.x;
    if (idx >= CM * 512) return;
    int d = idx & 511;
    int row = idx >> 9;
    int t = row & (CL - 1);
    float g = g_gate[row];
    const float* tf = g_ctab + (size_t)t * 1024 + d;
    const float* ts = tf + (size_t)CL * 1024;
    const float* tg = ts + (size_t)CL * 1024;
    float c = g * tf[0] + (1.f - g) * ts[0];
    float s = g * tf[512] + (1.f - g) * ts[512];
    float cg = tg[0], sg = tg[512];
    size_t lo = (size_t)row * CD + d, hi = lo + 512;
    float ql = Q[lo], qh = Q[hi];
    Q[lo] = tfr(ql * c - qh * s);
    Q[hi] = tfr(qh * c + ql * s);
    float kl = K[lo], kh = K[hi];
    K[lo] = tfr(kl * c - kh * s);
    K[hi] = tfr(kh * c + kl * s);
    float xl = z[lo], xh = z[hi];
    g_zglu[lo] = tfr(xl * cg - xh * sg);
    g_zglu[hi] = tfr(xh * cg + xl * sg);
}

// ---------------- fused causal softmax (16 heads serial) + head-mean; bf16 probs ----------------
__global__ __launch_bounds__(256) void smaw_kernel(float* __restrict__ aw) {
    const int l = blockIdx.x;
    const int b = blockIdx.y;
    const int n = l + 1;
    const int bound = ((l >> 7) + 1) << 7;     // 128-block boundary for attn_pv
    const int tid = threadIdx.x;
    const int lane = tid & 31, wid = tid >> 5;
    __shared__ float red[8];
    float4 awacc[2];
    awacc[0] = make_float4(0.f, 0.f, 0.f, 0.f);
    awacc[1] = make_float4(0.f, 0.f, 0.f, 0.f);
    const float NEG = -3.4e38f;

    for (int h = 0; h < CNH; h++) {
        float* row = g_S + ((size_t)(b * CNH + h) * CL + l) * CL;
        float4* row4 = (float4*)row;
        uint2* rowh2 = (uint2*)row;            // bf16 probs written in-place
        float4 v[2];
        float mx = NEG;
#pragma unroll
        for (int ii = 0; ii < 2; ii++) {
            int f4 = tid + ii * 256;
            int c0 = f4 * 4;
            if (c0 < n) {
                float4 tv = row4[f4];
                if (c0 + 1 >= n) tv.y = NEG;
                if (c0 + 2 >= n) tv.z = NEG;
                if (c0 + 3 >= n) tv.w = NEG;
                v[ii] = tv;
            } else {
                v[ii] = make_float4(NEG, NEG, NEG, NEG);
            }
            mx = fmaxf(mx, fmaxf(fmaxf(v[ii].x, v[ii].y), fmaxf(v[ii].z, v[ii].w)));
        }
#pragma unroll
        for (int o = 16; o > 0; o >>= 1) mx = fmaxf(mx, __shfl_xor_sync(~0u, mx, o));
        if (lane == 0) red[wid] = mx;
        __syncthreads();
        mx = red[0];
#pragma unroll
        for (int w = 1; w < 8; w++) mx = fmaxf(mx, red[w]);
        __syncthreads();

        float sum = 0.f;
#pragma unroll
        for (int ii = 0; ii < 2; ii++) {
            v[ii].x = expf(v[ii].x - mx);
            v[ii].y = expf(v[ii].y - mx);
            v[ii].z = expf(v[ii].z - mx);
            v[ii].w = expf(v[ii].w - mx);
            sum += v[ii].x + v[ii].y + v[ii].z + v[ii].w;
        }
#pragma unroll
        for (int o = 16; o > 0; o >>= 1) sum += __shfl_xor_sync(~0u, sum, o);
        if (lane == 0) red[wid] = sum;
        __syncthreads();
        sum = red[0];
#pragma unroll
        for (int w = 1; w < 8; w++) sum += red[w];
        __syncthreads();                       // all reads of this row complete
        float rinv = 1.f / sum;

#pragma unroll
        for (int ii = 0; ii < 2; ii++) {
            int f4 = tid + ii * 256;
            int c0 = f4 * 4;
            if (c0 < bound) {
                float4 p;
                p.x = v[ii].x * rinv; p.y = v[ii].y * rinv;
                p.z = v[ii].z * rinv; p.w = v[ii].w * rinv;
                awacc[ii].x += p.x; awacc[ii].y += p.y;
                awacc[ii].z += p.z; awacc[ii].w += p.w;
                uint2 pk;
                pk.x = pack_bf(p.x, p.y);
                pk.y = pack_bf(p.z, p.w);
                rowh2[f4] = pk;
            }
        }
        __syncthreads();                       // writes done before next head reuse of red[]
    }
    float4* awr4 = (float4*)(aw + ((size_t)b * CL + l) * CL);
    const float s16 = 1.f / CNH;
#pragma unroll
    for (int ii = 0; ii < 2; ii++) {
        int f4 = tid + ii * 256;
        float4 o;
        o.x = awacc[ii].x * s16; o.y = awacc[ii].y * s16;
        o.z = awacc[ii].z * s16; o.w = awacc[ii].w * s16;
        awr4[f4] = o;
    }
}

// ---------------- bilinear * (-nu) + LayerNorm (rounded out) ----------------
__global__ __launch_bounds__(256) void bilin_ln_kernel(
    float* __restrict__ U, const float* __restrict__ G,
    const float* __restrict__ ln_w, const float* __restrict__ ln_b)
{
    int row = blockIdx.x;
    int tid = threadIdx.x;
    size_t off = (size_t)row * CD;
    float nu = g_nu[row];
    __shared__ float red[256], red2[256];
    float a[4]; float s = 0.f, s2 = 0.f;
#pragma unroll
    for (int i = 0; i < 4; i++) {
        int d = tid + i * 256;
        float v = -nu * U[off + d] * G[off + d];
        a[i] = v; s += v; s2 += v * v;
    }
    red[tid] = s; red2[tid] = s2; __syncthreads();
    for (int st = 128; st > 0; st >>= 1) {
        if (tid < st) { red[tid] += red[tid + st]; red2[tid] += red2[tid + st]; }
        __syncthreads();
    }
    float mu = red[0] * (1.f / CD);
    float var = red2[0] * (1.f / CD) - mu * mu;
    float rstd = rsqrtf(var + 1e-5f);
#pragma unroll
    for (int i = 0; i < 4; i++) {
        int d = tid + i * 256;
        U[off + d] = tfr((a[i] - mu) * rstd * ln_w[d] + ln_b[d]);
    }
}

// ---------------- launcher ----------------
extern "C" void kernel_launch(void* const* d_in, const int* in_sizes, int n_in,
                              void* d_out, int out_size) {
    (void)in_sizes; (void)n_in; (void)out_size;
    const float* z     = (const float*)d_in[0];
    const float* Wq    = (const float*)d_in[1];
    const float* bq    = (const float*)d_in[2];
    const float* Wk    = (const float*)d_in[3];
    const float* bk    = (const float*)d_in[4];
    const float* Wv    = (const float*)d_in[5];
    const float* bv    = (const float*)d_in[6];
    const float* Wcoh  = (const float*)d_in[7];
    const float* gamma = (const float*)d_in[8];
    const float* rg_w1 = (const float*)d_in[9];
    const float* rg_b1 = (const float*)d_in[10];
    const float* rg_w2 = (const float*)d_in[11];
    const float* rg_b2 = (const float*)d_in[12];
    const float* nu_diff = (const float*)d_in[13];
    const float* nu_adv  = (const float*)d_in[14];
    const float* nu_w1 = (const float*)d_in[15];
    const float* nu_b1 = (const float*)d_in[16];
    const float* nu_w2 = (const float*)d_in[17];
    const float* nu_b2 = (const float*)d_in[18];
    const float* Wu    = (const float*)d_in[19];
    const float* bu    = (const float*)d_in[20];
    const float* Wg    = (const float*)d_in[21];
    const float* bg    = (const float*)d_in[22];
    const float* ln_w  = (const float*)d_in[23];
    const float* ln_b  = (const float*)d_in[24];
    const float* Cw    = (const float*)d_in[25];
    const float* Cb    = (const float*)d_in[26];

    float* out_z  = (float*)d_out;
    float* out_aw = out_z + (size_t)CM * CD;

    void* tmp;
    cudaGetSymbolAddress(&tmp, g_pool); float* pPool = (float*)tmp;
    cudaGetSymbolAddress(&tmp, g_QKV);  float* pQKV  = (float*)tmp;
    cudaGetSymbolAddress(&tmp, g_UG);   float* pUG   = (float*)tmp;
    cudaGetSymbolAddress(&tmp, g_Vh);   __nv_bfloat16* pVh = (__nv_bfloat16*)tmp;
    cudaGetSymbolAddress(&tmp, g_gk);   float* pGk   = (float*)tmp;
    cudaGetSymbolAddress(&tmp, g_zglu); float* pZg   = (float*)tmp;
    cudaGetSymbolAddress(&tmp, g_ao);   float* pAo   = (float*)tmp;
    cudaGetSymbolAddress(&tmp, g_zr);   float* pZr   = (float*)tmp;
    cudaGetSymbolAddress(&tmp, g_Wr);   float* pWr   = (float*)tmp;
    cudaGetSymbolAddress(&tmp, g_bcat); float* pBc   = (float*)tmp;
    cudaGetSymbolAddress(&tmp, g_gb);   float* pGb   = (float*)tmp;
    cudaGetSymbolAddress(&tmp, g_S);    float* pS    = (float*)tmp;

    float* pQ = pQKV;
    float* pK = pQKV + (size_t)CM * CD;
    float* pV = pQKV + 2 * (size_t)CM * CD;
    float* pU = pUG;
    float* pG = pUG + (size_t)CM * CD;

    float* rWq = pWr;                         // all transposed [N,K=1024]
    float* rWc = pWr + 3*1048576;
    float* rWu = pWr + 4*1048576;
    float* rCw = pWr + 6*1048576;
    float* rG1 = pWr + 7*1048576;             // rg_w1^T (256 x 1024)
    float* rN1 = pWr + 7*1048576 + 262144;    // nu_w1^T (128 x 1024)

    float* pHg = pS;                          // gate hidden (CM x 256) in g_S scratch
    float* pHn = pS + (size_t)CM * CHGATE;    // nu hidden   (CM x 128)

    const size_t SMEM  = 2 * 9216 * sizeof(float);   // 73728
    const size_t SMEMP = 2 * 14848;                  // 29696 (attn_pv, bf16)
    cudaFuncSetAttribute(tc_gemm<0,0>, cudaFuncAttributeMaxDynamicSharedMemorySize, (int)SMEM);
    cudaFuncSetAttribute(tc_gemm<0,1>, cudaFuncAttributeMaxDynamicSharedMemorySize, (int)SMEM);
    cudaFuncSetAttribute(tc_gemm<1,0>, cudaFuncAttributeMaxDynamicSharedMemorySize, (int)SMEM);
    cudaFuncSetAttribute(tc_gemm<2,0>, cudaFuncAttributeMaxDynamicSharedMemorySize, (int)SMEM);
    cudaFuncSetAttribute(tc_gemm<3,0>, cudaFuncAttributeMaxDynamicSharedMemorySize, (int)SMEM);
    cudaFuncSetAttribute(attn_pv, cudaFuncAttributeMaxDynamicSharedMemorySize, (int)SMEMP);

    dim3 gmain(CD / 128, CM / 128, 1);   // (8, 32)

    inv_kernel<<<1, 512>>>();                                        // 1

    TrArgs ta;
    ta.src[0]=Wq;   ta.dst[0]=rWq;              ta.N[0]=1024;
    ta.src[1]=Wk;   ta.dst[1]=pWr + 1048576;    ta.N[1]=1024;
    ta.src[2]=Wv;   ta.dst[2]=pWr + 2*1048576;  ta.N[2]=1024;
    ta.src[3]=Wcoh; ta.dst[3]=rWc;              ta.N[3]=1024;
    ta.src[4]=Wu;   ta.dst[4]=rWu;              ta.N[4]=1024;
    ta.src[5]=Wg;   ta.dst[5]=pWr + 5*1048576;  ta.N[5]=1024;
    ta.src[6]=Cw;   ta.dst[6]=rCw;              ta.N[6]=1024;
    ta.src[7]=rg_w1;ta.dst[7]=rG1;              ta.N[7]=256;
    ta.src[8]=nu_w1;ta.dst[8]=rN1;              ta.N[8]=128;
    ta.bsrc[0]=bq; ta.bsrc[1]=bk; ta.bsrc[2]=bv; ta.bsrc[3]=bu; ta.bsrc[4]=bg;
    ta.bdst = pBc;
    wtrans_kernel<<<dim3(32, 32, 10), dim3(32, 8)>>>(ta);            // 2
    round_kernel<<<2048, 256>>>(pZr, z, CM*CD);                      // 3

    // fused QKV: grid.z picks weight slice / bias slice / output slice   // 4 <- ncu
    tc_gemm<0,1><<<dim3(8, 32, 3), 256, SMEM>>>(pZr, rWq, pBc, pQKV,
        CD, CD, CD, CD,
        0, 0, 1048576, 0, (long)CM*CD, 0, 1024, 1,
        nullptr, nullptr, nullptr, nullptr);

    poolA_kernel<<<dim3(32, CB), 256>>>(z);                          // 5
    poolB_kernel<<<8, 256>>>();                                      // 6
    poolC_kernel<<<CM, 256>>>();                                     // 7
    ctab_kernel<<<(3 * CL * 512) / 256, 256>>>();                    // 8
    cvtV_kernel<<<CM*CD/1024, 256>>>(pV, pVh);                       // 9

    tc_gemm<0,1><<<gmain, 256, SMEM>>>(pPool, rWc, nullptr, pGk, CD, CD, CD, CD,
        0,0,0,0,0,0,0,1, nullptr, nullptr, nullptr, nullptr);

    // gate / nu hidden layers on tensor cores (output into g_S scratch)
    tc_gemm<0,0><<<dim3(CHGATE/128, CM/128, 1), 256, SMEM>>>(pPool, rG1, rg_b1, pHg,
        CD, CD, CD, CHGATE, 0,0,0,0,0,0,0,1, nullptr, nullptr, nullptr, nullptr);
    tc_gemm<0,0><<<dim3(CHNU/128, CM/128, 1), 256, SMEM>>>(pPool, rN1, nu_b1, pHn,
        CD, CD, CD, CHNU, 0,0,0,0,0,0,0,1, nullptr, nullptr, nullptr, nullptr);
    gate2_kernel<<<CM/8, 256>>>(pHg, rg_w2, rg_b2);
    nu2_kernel<<<CM/8, 256>>>(pHn, nu_w2, nu_b2, nu_diff, nu_adv);

    // coherence bias: gb[b] = tanh(gamma)/32 * gk[b] @ K_raw[b]^T
    tc_gemm<2,0><<<dim3(CL/128, CL/128, CB), 256, SMEM>>>(pGk, pK, nullptr, pGb,
        CD, CD, CD, CL,
        (long)CL*CD, 0, (long)CL*CD, 0, (long)CL*CL, 0, 0, 1,
        nullptr, nullptr, gamma, nullptr);

    rope_all_kernel<<<(CM * 512) / 256, 256>>>(z, pQ, pK);

    // fused U/G
    tc_gemm<0,0><<<dim3(8, 32, 2), 256, SMEM>>>(pZg, rWu, pBc + 3*1024, pUG,
        CD, CD, CD, CD,
        0, 0, 1048576, 0, (long)CM*CD, 0, 1024, 1,
        nullptr, nullptr, nullptr, nullptr);

    // logits: S[b,h] = 0.125 * Qr_h @ Kr_h^T + gb[b], causal block skip
    tc_gemm<3,0><<<dim3(CL/128, CL/128, CB*CNH), 256, SMEM>>>(pQ, pK, nullptr, pS,
        CHD, CD, CD, CL,
        (long)CL*CD, CHD, (long)CL*CD, CHD, (long)CL*CL, (long)CL*CL, 0, CNH,
        nullptr, nullptr, nullptr, pGb);

    smaw_kernel<<<dim3(CL, CB), 256>>>(out_aw);
    attn_pv<<<dim3(CL/128, CNH, CB), 256, SMEMP>>>(pVh);

    bilin_ln_kernel<<<CM, 256>>>(pU, pG, ln_w, ln_b);
    tc_gemm<1,0><<<gmain, 256, SMEM>>>(pU, rCw, Cb, out_z, CD, CD, CD, CD,
        0,0,0,0,0,0,0,1, z, pAo, nullptr, nullptr);
}

// round 12
// speedup vs baseline: 1.6754x; 1.0563x over previous
#include <cuda_runtime.h>
#include <cuda_bf16.h>
#include <math.h>
#include <stdint.h>

#define CB 2
#define CL 2048
#define CD 1024
#define CNH 16
#define CHD 64
#define CM (CB*CL)          // 4096 rows
#define CHGATE 256
#define CHNU 128

// ---------------- scratch (device globals; allocation-free rule) ----------------
__device__ float g_pool[CM*CD];
__device__ float g_QKV[3*CM*CD];  // Q | K | V
__device__ float g_UG[2*CM*CD];   // U | G (adv_n written back into U slice)
__device__ __nv_bfloat16 g_Vh[CM*CD]; // bf16 V for attn_pv
__device__ float g_gk[CM*CD];
__device__ float g_zglu[CM*CD];
__device__ float g_ao[CM*CD];     // attention output
__device__ float g_zr[CM*CD];     // tf32-rounded z
__device__ float g_Wr[7*1048576 + 393216]; // transposed+rounded weights [N,K]
__device__ float g_bcat[5*1024];  // bq|bk|bv|bu|bg
__device__ float g_gb[CB*CL*CL];  // coherence bias (causal blocks only)
__device__ float g_S[134217728];  // (B,NH,L,L) logits (fp32) -> probs (bf16 in-place)
__device__ float g_gate[CM];
__device__ float g_nu[CM];
__device__ float g_csum[CB*32*CD];// pool chunk sums
__device__ float g_ctab[3*CL*1024]; // rope tables: [base][t][cos512|sin512]
__device__ double g_invd[1536];   // inv freqs: [fast | slow | glu] x 512

// ---------------- helpers ----------------
__device__ __forceinline__ unsigned f2tf(float x) {
    unsigned r; asm("cvt.rna.tf32.f32 %0, %1;" : "=r"(r) : "f"(x)); return r;
}
__device__ __forceinline__ float tfr(float x) { return __uint_as_float(f2tf(x)); }
__device__ __forceinline__ void cpa16(float* s, const float* g) {
    unsigned sa = (unsigned)__cvta_generic_to_shared(s);
    asm volatile("cp.async.cg.shared.global [%0], [%1], 16;" :: "r"(sa), "l"(g));
}
__device__ __forceinline__ void cpa16b(void* s, const void* g) {
    unsigned sa = (unsigned)__cvta_generic_to_shared(s);
    asm volatile("cp.async.cg.shared.global [%0], [%1], 16;" :: "r"(sa), "l"(g));
}
__device__ __forceinline__ void mma8(float* d, const unsigned* a, const unsigned* b) {
    asm volatile(
        "mma.sync.aligned.m16n8k8.row.col.f32.tf32.tf32.f32 "
        "{%0,%1,%2,%3},{%4,%5,%6,%7},{%8,%9},{%0,%1,%2,%3};"
        : "+f"(d[0]), "+f"(d[1]), "+f"(d[2]), "+f"(d[3])
        : "r"(a[0]), "r"(a[1]), "r"(a[2]), "r"(a[3]), "r"(b[0]), "r"(b[1]));
}
__device__ __forceinline__ void mma16(float* d, const unsigned* a, const unsigned* b) {
    asm volatile(
        "mma.sync.aligned.m16n8k16.row.col.f32.bf16.bf16.f32 "
        "{%0,%1,%2,%3},{%4,%5,%6,%7},{%8,%9},{%0,%1,%2,%3};"
        : "+f"(d[0]), "+f"(d[1]), "+f"(d[2]), "+f"(d[3])
        : "r"(a[0]), "r"(a[1]), "r"(a[2]), "r"(a[3]), "r"(b[0]), "r"(b[1]));
}
__device__ __forceinline__ void ldsm4(unsigned* r, unsigned addr) {
    asm volatile("ldmatrix.sync.aligned.m8n8.x4.shared.b16 {%0,%1,%2,%3}, [%4];"
        : "=r"(r[0]), "=r"(r[1]), "=r"(r[2]), "=r"(r[3]) : "r"(addr));
}
__device__ __forceinline__ void ldsm4t(unsigned* r, unsigned addr) {
    asm volatile("ldmatrix.sync.aligned.m8n8.x4.trans.shared.b16 {%0,%1,%2,%3}, [%4];"
        : "=r"(r[0]), "=r"(r[1]), "=r"(r[2]), "=r"(r[3]) : "r"(addr));
}
__device__ __forceinline__ unsigned pack_bf(float a, float b) {
    __nv_bfloat162 h = __floats2bfloat162_rn(a, b);
    return *(unsigned*)&h;
}

// ---------------- weight transpose + round (+ bias concat z=9, z-round z=10) ----------------
struct TrArgs { const float* src[9]; float* dst[9]; int N[9];
                const float* bsrc[5]; float* bdst;
                const float* zsrc; float* zdst; };
__global__ void wtrans_kernel(TrArgs a) {
    const int w = blockIdx.z;
    if (w == 9) {
        int i = blockIdx.x;
        if (i < 5 && blockIdx.y == 0) {
            int t = threadIdx.y * 32 + threadIdx.x;
#pragma unroll
            for (int j = 0; j < 4; j++)
                a.bdst[i * 1024 + t + j * 256] = a.bsrc[i][t + j * 256];
        }
        return;
    }
    if (w == 10) {
        // round z -> zr: 1024 blocks x 256 threads x 16 elems
        int blk = blockIdx.y * 32 + blockIdx.x;
        int t = threadIdx.y * 32 + threadIdx.x;
        size_t base = (size_t)blk * 4096 + t;
#pragma unroll
        for (int j = 0; j < 16; j++)
            a.zdst[base + j * 256] = tfr(a.zsrc[base + j * 256]);
        return;
    }
    const int N = a.N[w];
    const int nx = blockIdx.x * 32;
    if (nx >= N) return;
    const int ky = blockIdx.y * 32;
    __shared__ float t[32][33];
    const float* src = a.src[w];
    const int tx = threadIdx.x, ty = threadIdx.y;   // 32 x 8
#pragma unroll
    for (int i = 0; i < 4; i++)
        t[ty + 8*i][tx] = src[(size_t)(ky + ty + 8*i) * N + nx + tx];
    __syncthreads();
    float* dst = a.dst[w];
#pragma unroll
    for (int i = 0; i < 4; i++)
        dst[(size_t)(nx + ty + 8*i) * 1024 + ky + tx] = tfr(t[tx][ty + 8*i]);
}

__global__ void cvtV_kernel(const float* __restrict__ v, __nv_bfloat16* __restrict__ o) {
    int i = blockIdx.x * 256 + threadIdx.x;
    float4 x = ((const float4*)v)[i];
    uint2 u;
    u.x = pack_bf(x.x, x.y);
    u.y = pack_bf(x.z, x.w);
    ((uint2*)o)[i] = u;
}

// ---------------- tensor-core GEMM: 128x128x32 tiles, tf32, full-LDSM ----------------
// C = A[M,K] @ B[N,K]^T   (both operands K-major)
// MODE 0: C = acc + bias(optional, +z*sBz); RND rounds output to tf32
// MODE 1: C = r1 + 0.42*r2 + 1.07*(acc + bias)
// MODE 2: C = tanh(gamma)/32 * acc, causal blockskip
// MODE 3: C = 0.125*acc + gb[l,m], causal blockskip
template<int MODE, int RND>
__global__ __launch_bounds__(256, 2) void tc_gemm(
    const float* __restrict__ A, const float* __restrict__ Bm,
    const float* __restrict__ bias, float* __restrict__ C,
    int K, int lda, int ldb, int ldc,
    long sAo, long sAi, long sBo, long sBi, long sCz, long sGo, long sBz, int zdiv,
    const float* __restrict__ r1, const float* __restrict__ r2,
    const float* __restrict__ gamma, const float* __restrict__ gbb)
{
    const int bm = blockIdx.y * 128, bn = blockIdx.x * 128;
    if ((MODE == 2 || MODE == 3) && bn >= bm + 128) return;   // causal-dead block
    const int z = blockIdx.z;
    const int zo = z / zdiv, zi = z - zo * zdiv;
    A  += (size_t)zo * sAo + (size_t)zi * sAi;
    Bm += (size_t)zo * sBo + (size_t)zi * sBi;
    C  += (size_t)z * sCz;
    if (bias) bias += (size_t)z * sBz;
    const float* gbp = (MODE == 3) ? (gbb + (size_t)zo * sGo) : nullptr;

    extern __shared__ float sm[];
    const int STG = 9216;
    float* Asm[2] = { sm, sm + STG };
    float* Bsm[2] = { sm + 4608, sm + STG + 4608 };

    const int t = threadIdx.x;
    const int wid = t >> 5, lane = t & 31;
    const int wm = (wid >> 2) * 64, wn = (wid & 3) * 32;
    const int g = lane >> 2, tig = lane & 3;

    const unsigned aoff = ((lane & 15) * 36 + (lane >> 4) * 4) * 4;
    const unsigned boff = ((lane & 7) * 36 + ((lane >> 3) & 1) * 4 + (lane >> 4) * (8 * 36)) * 4;

    float acc[4][4][4];
#pragma unroll
    for (int i = 0; i < 4; i++)
#pragma unroll
        for (int j = 0; j < 4; j++)
#pragma unroll
            for (int q = 0; q < 4; q++) acc[i][j][q] = 0.f;

    auto loadT = [&](float* s, const float* G, int ld, int base, int k0) {
        int r = t >> 3, k4 = (t & 7) * 4;
#pragma unroll
        for (int it = 0; it < 4; it++)
            cpa16(s + (r + it*32)*36 + k4,
                  G + (size_t)(base + r + it*32) * ld + k0 + k4);
    };

    const int NT = K >> 5;
    loadT(Asm[0], A, lda, bm, 0);
    loadT(Bsm[0], Bm, ldb, bn, 0);
    asm volatile("cp.async.commit_group;");

    for (int kt = 0; kt < NT; kt++) {
        if (kt + 1 < NT) {
            loadT(Asm[(kt+1)&1], A, lda, bm, (kt+1)*32);
            loadT(Bsm[(kt+1)&1], Bm, ldb, bn, (kt+1)*32);
            asm volatile("cp.async.commit_group;");
            asm volatile("cp.async.wait_group 1;");
        } else {
            asm volatile("cp.async.wait_group 0;");
        }
        __syncthreads();
        const unsigned Au = (unsigned)__cvta_generic_to_shared(Asm[kt&1]);
        const unsigned Bu = (unsigned)__cvta_generic_to_shared(Bsm[kt&1]);
#pragma unroll
        for (int ks = 0; ks < 4; ks++) {
            const int k = ks * 8;
            unsigned af[4][4];
#pragma unroll
            for (int i = 0; i < 4; i++)
                ldsm4(af[i], Au + ((wm + 16*i) * 36 + k) * 4 + aoff);
            unsigned bf[4][2];
#pragma unroll
            for (int jj = 0; jj < 2; jj++) {
                unsigned r4[4];
                ldsm4(r4, Bu + ((wn + 16*jj) * 36 + k) * 4 + boff);
                bf[2*jj][0]   = r4[0];
                bf[2*jj][1]   = r4[1];
                bf[2*jj+1][0] = r4[2];
                bf[2*jj+1][1] = r4[3];
            }
#pragma unroll
            for (int i = 0; i < 4; i++)
#pragma unroll
                for (int j = 0; j < 4; j++)
                    mma8(acc[i][j], af[i], bf[j]);
        }
        __syncthreads();
    }

    float scale = 1.f;
    if (MODE == 2) scale = tanhf(gamma[0]) * 0.03125f;
    if (MODE == 3) scale = 0.125f;
#pragma unroll
    for (int i = 0; i < 4; i++) {
        const int r0 = bm + wm + 16*i + g;
#pragma unroll
        for (int j = 0; j < 4; j++) {
            const int c0 = bn + wn + 8*j + 2*tig;
#pragma unroll
            for (int h2 = 0; h2 < 2; h2++) {
                const int rr = r0 + h2*8;
                float v0 = acc[i][j][h2*2], v1 = acc[i][j][h2*2+1];
                const size_t off = (size_t)rr * ldc + c0;
                if (MODE == 0) {
                    if (bias) { v0 += bias[c0]; v1 += bias[c0+1]; }
                    if (RND) { v0 = tfr(v0); v1 = tfr(v1); }
                    C[off] = v0; C[off+1] = v1;
                } else if (MODE == 1) {
                    C[off]   = r1[off]   + 0.42f*r2[off]   + 1.07f*(v0 + bias[c0]);
                    C[off+1] = r1[off+1] + 0.42f*r2[off+1] + 1.07f*(v1 + bias[c0+1]);
                } else if (MODE == 2) {
                    C[off] = tfr(v0*scale); C[off+1] = tfr(v1*scale);
                } else {
                    const size_t go = (size_t)rr * CL + c0;
                    C[off]   = v0*scale + gbp[go];
                    C[off+1] = v1*scale + gbp[go+1];
                }
            }
        }
    }
}

// ---------------- attn_out = P(bf16) @ V(bf16), m16n8k16 MMA, causal ----------------
__global__ __launch_bounds__(256) void attn_pv(const __nv_bfloat16* __restrict__ Vh) {
    const int l0 = blockIdx.x * 128;
    const int h = blockIdx.y, b = blockIdx.z;
    const char* Sb = (const char*)g_S + (((size_t)(b * CNH + h) * CL + l0) * CL) * 4;
    const __nv_bfloat16* V = Vh + (size_t)b * CL * CD + h * CHD;
    float* O = g_ao + (size_t)b * CL * CD + h * CHD;

    extern __shared__ char smc[];
    const int STG = 14848;                    // S 128*80 + V 32*144
    char* Ss[2] = { smc, smc + STG };
    char* Vs[2] = { smc + 10240, smc + STG + 10240 };

    const int t = threadIdx.x;
    const int wid = t >> 5, lane = t & 31;
    const int wm = wid * 16;
    const int g = lane >> 2, tig = lane & 3;
    const int mrow = ((lane >> 3) & 1) * 8 + (lane & 7);
    const int mcb  = ((lane >> 4) & 1) * 16;

    float acc[8][4];
#pragma unroll
    for (int j = 0; j < 8; j++)
#pragma unroll
        for (int q = 0; q < 4; q++) acc[j][q] = 0.f;

    auto loadS = [&](char* s, int k0) {
#pragma unroll
        for (int j = 0; j < 2; j++) {
            int a = t * 2 + j;
            int row = a >> 2, ch = a & 3;
            cpa16b(s + row * 80 + ch * 16,
                   Sb + (size_t)row * CL * 4 + k0 * 2 + ch * 16);
        }
    };
    auto loadV = [&](char* s, int k0) {
        int row = t >> 3, ch = t & 7;
        cpa16b(s + row * 144 + ch * 16,
               (const char*)(V + (size_t)(k0 + row) * CD) + ch * 16);
    };

    const int NT = (l0 + 128) >> 5;
    loadS(Ss[0], 0); loadV(Vs[0], 0);
    asm volatile("cp.async.commit_group;");

    for (int kt = 0; kt < NT; kt++) {
        if (kt + 1 < NT) {
            loadS(Ss[(kt+1)&1], (kt+1)*32);
            loadV(Vs[(kt+1)&1], (kt+1)*32);
            asm volatile("cp.async.commit_group;");
            asm volatile("cp.async.wait_group 1;");
        } else {
            asm volatile("cp.async.wait_group 0;");
        }
        __syncthreads();
        const unsigned Su = (unsigned)__cvta_generic_to_shared(Ss[kt&1]);
        const unsigned Vu = (unsigned)__cvta_generic_to_shared(Vs[kt&1]);
#pragma unroll
        for (int ks = 0; ks < 2; ks++) {
            unsigned af[4];
            ldsm4(af, Su + (wm + mrow) * 80 + ks * 32 + mcb);
            unsigned bf[8][2];
#pragma unroll
            for (int nt = 0; nt < 4; nt++) {
                unsigned r4[4];
                ldsm4t(r4, Vu + (ks * 16 + mrow) * 144 + nt * 32 + mcb);
                bf[2*nt][0]   = r4[0];
                bf[2*nt][1]   = r4[1];
                bf[2*nt+1][0] = r4[2];
                bf[2*nt+1][1] = r4[3];
            }
#pragma unroll
            for (int j = 0; j < 8; j++)
                mma16(acc[j], af, bf[j]);
        }
        __syncthreads();
    }
#pragma unroll
    for (int j = 0; j < 8; j++) {
        const int c0 = 8*j + 2*tig;
#pragma unroll
        for (int h2 = 0; h2 < 2; h2++) {
            const int rr = l0 + wm + g + h2*8;
            O[(size_t)rr * CD + c0]     = acc[j][h2*2];
            O[(size_t)rr * CD + c0 + 1] = acc[j][h2*2 + 1];
        }
    }
}

// ---------------- rope helpers ----------------
__global__ void inv_kernel() {
    int d = threadIdx.x;
    double e = (double)(2 * d) / (double)CD;
    g_invd[d]        = pow(1.6180339887498948482, -e);
    g_invd[512 + d]  = pow(1618.0, -e);
    g_invd[1024 + d] = pow(16180.0, -e);
}

__device__ __forceinline__ void rope_cs(double inv, int t, float* c, float* s) {
    double ang = (double)t * inv;
    double k = floor(ang * 0.15915494309189533576888376337251436);
    float a = (float)(ang - k * 6.28318530717958647692528676655900577);
    sincosf(a, s, c);
}

__global__ void ctab_kernel() {
    int idx = blockIdx.x * blockDim.x + threadIdx.x;
    int d = idx & 511;
    int t = (idx >> 9) & (CL - 1);
    int base = idx >> 20;
    float c, s;
    rope_cs(g_invd[base * 512 + d], t, &c, &s);
    float* o = g_ctab + (size_t)base * CL * 1024 + t * 1024;
    o[d] = c;
    o[d + 512] = s;
}

// ---------------- causal cumulative mean: 3-phase parallel scan ----------------
__global__ void poolA_kernel(const float* __restrict__ z) {
    const int c = blockIdx.x, b = blockIdx.y;
    const int t = threadIdx.x;
    const float4* zp = (const float4*)(z + ((size_t)b * CL + c * 64) * CD);
    float4* pp = (float4*)(g_pool + ((size_t)b * CL + c * 64) * CD);
    float4 acc = make_float4(0.f, 0.f, 0.f, 0.f);
    for (int r = 0; r < 64; r++) {
        float4 v = zp[r * 256 + t];
        acc.x += v.x; acc.y += v.y; acc.z += v.z; acc.w += v.w;
        pp[r * 256 + t] = acc;
    }
    ((float4*)g_csum)[((size_t)b * 32 + c) * 256 + t] = acc;
}
__global__ void poolB_kernel() {
    int idx = blockIdx.x * 256 + threadIdx.x;
    int b = idx >> 10, d = idx & 1023;
    float run = 0.f;
    for (int c = 0; c < 32; c++) {
        size_t o = ((size_t)b * 32 + c) * CD + d;
        float v = g_csum[o];
        g_csum[o] = run;
        run += v;
    }
}
__global__ void poolC_kernel() {
    size_t idx = (size_t)blockIdx.x * 256 + threadIdx.x;
    int row = (int)(idx >> 8);
    int f4 = (int)(idx & 255);
    int b = row >> 11, l = row & (CL - 1), c = l >> 6;
    float4 off = ((const float4*)g_csum)[((size_t)(b * 32 + c)) * 256 + f4];
    float4 v = ((float4*)g_pool)[idx];
    float inv = 1.f / (float)(l + 1);
    v.x = tfr((v.x + off.x) * inv);
    v.y = tfr((v.y + off.y) * inv);
    v.z = tfr((v.z + off.z) * inv);
    v.w = tfr((v.w + off.w) * inv);
    ((float4*)g_pool)[idx] = v;
}

// ---------------- merged gate/nu epilogue ----------------
__global__ __launch_bounds__(256) void gatenu_kernel(
    const float* __restrict__ ghid, const float* __restrict__ gw2, const float* __restrict__ gb2,
    const float* __restrict__ nhid, const float* __restrict__ nw2, const float* __restrict__ nb2,
    const float* __restrict__ nu_diff, const float* __restrict__ nu_adv)
{
    int row = blockIdx.x * 8 + (threadIdx.x >> 5);
    int lane = threadIdx.x & 31;
    if (blockIdx.y == 0) {
        const float* hr = ghid + (size_t)row * CHGATE;
        float acc = 0.f;
#pragma unroll
        for (int j = 0; j < 8; j++) {
            int c = lane + j * 32;
            float x = hr[c];
            float h = 0.5f * x * (1.f + erff(x * 0.7071067811865476f));
            acc += h * gw2[c];
        }
#pragma unroll
        for (int o = 16; o > 0; o >>= 1) acc += __shfl_xor_sync(~0u, acc, o);
        if (lane == 0) {
            float y = acc + gb2[0];
            g_gate[row] = 1.f / (1.f + expf(-y));
        }
    } else {
        const float* hr = nhid + (size_t)row * CHNU;
        float acc = 0.f;
#pragma unroll
        for (int j = 0; j < 4; j++) {
            int c = lane + j * 32;
            acc += tanhf(hr[c]) * nw2[c];
        }
#pragma unroll
        for (int o = 16; o > 0; o >>= 1) acc += __shfl_xor_sync(~0u, acc, o);
        if (lane == 0) {
            g_nu[row] = fabsf(nu_diff[0]) + tanhf(acc + nb2[0]) * fabsf(nu_adv[0]);
        }
    }
}

// ---------------- merged RoPE from tables: Q/K in-place + zglu write ----------------
__global__ void rope_all_kernel(const float* __restrict__ z,
                                float* __restrict__ Q, float* __restrict__ K) {
    int idx = blockIdx.x * blockDim.x + threadIdx.x;
    if (idx >= CM * 512) return;
    int d = idx & 511;
    int row = idx >> 9;
    int t = row & (CL - 1);
    float g = g_gate[row];
    const float* tf = g_ctab + (size_t)t * 1024 + d;
    const float* ts = tf + (size_t)CL * 1024;
    const float* tg = ts + (size_t)CL * 1024;
    float c = g * tf[0] + (1.f - g) * ts[0];
    float s = g * tf[512] + (1.f - g) * ts[512];
    float cg = tg[0], sg = tg[512];
    size_t lo = (size_t)row * CD + d, hi = lo + 512;
    float ql = Q[lo], qh = Q[hi];
    Q[lo] = tfr(ql * c - qh * s);
    Q[hi] = tfr(qh * c + ql * s);
    float kl = K[lo], kh = K[hi];
    K[lo] = tfr(kl * c - kh * s);
    K[hi] = tfr(kh * c + kl * s);
    float xl = z[lo], xh = z[hi];
    g_zglu[lo] = tfr(xl * cg - xh * sg);
    g_zglu[hi] = tfr(xh * cg + xl * sg);
}

// ---------------- fused causal softmax (16 heads serial) + head-mean; bf16 probs ----------------
__global__ __launch_bounds__(256) void smaw_kernel(float* __restrict__ aw) {
    const int l = blockIdx.x;
    const int b = blockIdx.y;
    const int n = l + 1;
    const int bound = ((l >> 7) + 1) << 7;
    const int tid = threadIdx.x;
    const int lane = tid & 31, wid = tid >> 5;
    __shared__ float red[8];
    float4 awacc[2];
    awacc[0] = make_float4(0.f, 0.f, 0.f, 0.f);
    awacc[1] = make_float4(0.f, 0.f, 0.f, 0.f);
    const float NEG = -3.4e38f;

    for (int h = 0; h < CNH; h++) {
        float* row = g_S + ((size_t)(b * CNH + h) * CL + l) * CL;
        float4* row4 = (float4*)row;
        uint2* rowh2 = (uint2*)row;
        float4 v[2];
        float mx = NEG;
#pragma unroll
        for (int ii = 0; ii < 2; ii++) {
            int f4 = tid + ii * 256;
            int c0 = f4 * 4;
            if (c0 < n) {
                float4 tv = row4[f4];
                if (c0 + 1 >= n) tv.y = NEG;
                if (c0 + 2 >= n) tv.z = NEG;
                if (c0 + 3 >= n) tv.w = NEG;
                v[ii] = tv;
            } else {
                v[ii] = make_float4(NEG, NEG, NEG, NEG);
            }
            mx = fmaxf(mx, fmaxf(fmaxf(v[ii].x, v[ii].y), fmaxf(v[ii].z, v[ii].w)));
        }
#pragma unroll
        for (int o = 16; o > 0; o >>= 1) mx = fmaxf(mx, __shfl_xor_sync(~0u, mx, o));
        if (lane == 0) red[wid] = mx;
        __syncthreads();
        mx = red[0];
#pragma unroll
        for (int w = 1; w < 8; w++) mx = fmaxf(mx, red[w]);
        __syncthreads();

        float sum = 0.f;
#pragma unroll
        for (int ii = 0; ii < 2; ii++) {
            v[ii].x = expf(v[ii].x - mx);
            v[ii].y = expf(v[ii].y - mx);
            v[ii].z = expf(v[ii].z - mx);
            v[ii].w = expf(v[ii].w - mx);
            sum += v[ii].x + v[ii].y + v[ii].z + v[ii].w;
        }
#pragma unroll
        for (int o = 16; o > 0; o >>= 1) sum += __shfl_xor_sync(~0u, sum, o);
        if (lane == 0) red[wid] = sum;
        __syncthreads();
        sum = red[0];
#pragma unroll
        for (int w = 1; w < 8; w++) sum += red[w];
        __syncthreads();
        float rinv = 1.f / sum;

#pragma unroll
        for (int ii = 0; ii < 2; ii++) {
            int f4 = tid + ii * 256;
            int c0 = f4 * 4;
            if (c0 < bound) {
                float4 p;
                p.x = v[ii].x * rinv; p.y = v[ii].y * rinv;
                p.z = v[ii].z * rinv; p.w = v[ii].w * rinv;
                awacc[ii].x += p.x; awacc[ii].y += p.y;
                awacc[ii].z += p.z; awacc[ii].w += p.w;
                uint2 pk;
                pk.x = pack_bf(p.x, p.y);
                pk.y = pack_bf(p.z, p.w);
                rowh2[f4] = pk;
            }
        }
        __syncthreads();
    }
    float4* awr4 = (float4*)(aw + ((size_t)b * CL + l) * CL);
    const float s16 = 1.f / CNH;
#pragma unroll
    for (int ii = 0; ii < 2; ii++) {
        int f4 = tid + ii * 256;
        float4 o;
        o.x = awacc[ii].x * s16; o.y = awacc[ii].y * s16;
        o.z = awacc[ii].z * s16; o.w = awacc[ii].w * s16;
        awr4[f4] = o;
    }
}

// ---------------- bilinear * (-nu) + LayerNorm (rounded out) ----------------
__global__ __launch_bounds__(256) void bilin_ln_kernel(
    float* __restrict__ U, const float* __restrict__ G,
    const float* __restrict__ ln_w, const float* __restrict__ ln_b)
{
    int row = blockIdx.x;
    int tid = threadIdx.x;
    size_t off = (size_t)row * CD;
    float nu = g_nu[row];
    __shared__ float red[256], red2[256];
    float a[4]; float s = 0.f, s2 = 0.f;
#pragma unroll
    for (int i = 0; i < 4; i++) {
        int d = tid + i * 256;
        float v = -nu * U[off + d] * G[off + d];
        a[i] = v; s += v; s2 += v * v;
    }
    red[tid] = s; red2[tid] = s2; __syncthreads();
    for (int st = 128; st > 0; st >>= 1) {
        if (tid < st) { red[tid] += red[tid + st]; red2[tid] += red2[tid + st]; }
        __syncthreads();
    }
    float mu = red[0] * (1.f / CD);
    float var = red2[0] * (1.f / CD) - mu * mu;
    float rstd = rsqrtf(var + 1e-5f);
#pragma unroll
    for (int i = 0; i < 4; i++) {
        int d = tid + i * 256;
        U[off + d] = tfr((a[i] - mu) * rstd * ln_w[d] + ln_b[d]);
    }
}

// ---------------- launcher ----------------
extern "C" void kernel_launch(void* const* d_in, const int* in_sizes, int n_in,
                              void* d_out, int out_size) {
    (void)in_sizes; (void)n_in; (void)out_size;
    const float* z     = (const float*)d_in[0];
    const float* Wq    = (const float*)d_in[1];
    const float* bq    = (const float*)d_in[2];
    const float* Wk    = (const float*)d_in[3];
    const float* bk    = (const float*)d_in[4];
    const float* Wv    = (const float*)d_in[5];
    const float* bv    = (const float*)d_in[6];
    const float* Wcoh  = (const float*)d_in[7];
    const float* gamma = (const float*)d_in[8];
    const float* rg_w1 = (const float*)d_in[9];
    const float* rg_b1 = (const float*)d_in[10];
    const float* rg_w2 = (const float*)d_in[11];
    const float* rg_b2 = (const float*)d_in[12];
    const float* nu_diff = (const float*)d_in[13];
    const float* nu_adv  = (const float*)d_in[14];
    const float* nu_w1 = (const float*)d_in[15];
    const float* nu_b1 = (const float*)d_in[16];
    const float* nu_w2 = (const float*)d_in[17];
    const float* nu_b2 = (const float*)d_in[18];
    const float* Wu    = (const float*)d_in[19];
    const float* bu    = (const float*)d_in[20];
    const float* Wg    = (const float*)d_in[21];
    const float* bg    = (const float*)d_in[22];
    const float* ln_w  = (const float*)d_in[23];
    const float* ln_b  = (const float*)d_in[24];
    const float* Cw    = (const float*)d_in[25];
    const float* Cb    = (const float*)d_in[26];

    float* out_z  = (float*)d_out;
    float* out_aw = out_z + (size_t)CM * CD;

    void* tmp;
    cudaGetSymbolAddress(&tmp, g_pool); float* pPool = (float*)tmp;
    cudaGetSymbolAddress(&tmp, g_QKV);  float* pQKV  = (float*)tmp;
    cudaGetSymbolAddress(&tmp, g_UG);   float* pUG   = (float*)tmp;
    cudaGetSymbolAddress(&tmp, g_Vh);   __nv_bfloat16* pVh = (__nv_bfloat16*)tmp;
    cudaGetSymbolAddress(&tmp, g_gk);   float* pGk   = (float*)tmp;
    cudaGetSymbolAddress(&tmp, g_zglu); float* pZg   = (float*)tmp;
    cudaGetSymbolAddress(&tmp, g_ao);   float* pAo   = (float*)tmp;
    cudaGetSymbolAddress(&tmp, g_zr);   float* pZr   = (float*)tmp;
    cudaGetSymbolAddress(&tmp, g_Wr);   float* pWr   = (float*)tmp;
    cudaGetSymbolAddress(&tmp, g_bcat); float* pBc   = (float*)tmp;
    cudaGetSymbolAddress(&tmp, g_gb);   float* pGb   = (float*)tmp;
    cudaGetSymbolAddress(&tmp, g_S);    float* pS    = (float*)tmp;

    float* pQ = pQKV;
    float* pK = pQKV + (size_t)CM * CD;
    float* pV = pQKV + 2 * (size_t)CM * CD;
    float* pU = pUG;
    float* pG = pUG + (size_t)CM * CD;

    float* rWq = pWr;                         // all transposed [N,K=1024]
    float* rWc = pWr + 3*1048576;
    float* rWu = pWr + 4*1048576;
    float* rCw = pWr + 6*1048576;
    float* rG1 = pWr + 7*1048576;
    float* rN1 = pWr + 7*1048576 + 262144;

    float* pHg = pS;                          // gate hidden (CM x 256) in g_S scratch
    float* pHn = pS + (size_t)CM * CHGATE;    // nu hidden   (CM x 128)

    const size_t SMEM  = 2 * 9216 * sizeof(float);   // 73728
    const size_t SMEMP = 2 * 14848;                  // 29696 (attn_pv, bf16)
    cudaFuncSetAttribute(tc_gemm<0,0>, cudaFuncAttributeMaxDynamicSharedMemorySize, (int)SMEM);
    cudaFuncSetAttribute(tc_gemm<0,1>, cudaFuncAttributeMaxDynamicSharedMemorySize, (int)SMEM);
    cudaFuncSetAttribute(tc_gemm<1,0>, cudaFuncAttributeMaxDynamicSharedMemorySize, (int)SMEM);
    cudaFuncSetAttribute(tc_gemm<2,0>, cudaFuncAttributeMaxDynamicSharedMemorySize, (int)SMEM);
    cudaFuncSetAttribute(tc_gemm<3,0>, cudaFuncAttributeMaxDynamicSharedMemorySize, (int)SMEM);
    cudaFuncSetAttribute(attn_pv, cudaFuncAttributeMaxDynamicSharedMemorySize, (int)SMEMP);

    dim3 gmain(CD / 128, CM / 128, 1);   // (8, 32)

    inv_kernel<<<1, 512>>>();                                        // 1

    TrArgs ta;
    ta.src[0]=Wq;   ta.dst[0]=rWq;              ta.N[0]=1024;
    ta.src[1]=Wk;   ta.dst[1]=pWr + 1048576;    ta.N[1]=1024;
    ta.src[2]=Wv;   ta.dst[2]=pWr + 2*1048576;  ta.N[2]=1024;
    ta.src[3]=Wcoh; ta.dst[3]=rWc;              ta.N[3]=1024;
    ta.src[4]=Wu;   ta.dst[4]=rWu;              ta.N[4]=1024;
    ta.src[5]=Wg;   ta.dst[5]=pWr + 5*1048576;  ta.N[5]=1024;
    ta.src[6]=Cw;   ta.dst[6]=rCw;              ta.N[6]=1024;
    ta.src[7]=rg_w1;ta.dst[7]=rG1;              ta.N[7]=256;
    ta.src[8]=nu_w1;ta.dst[8]=rN1;              ta.N[8]=128;
    ta.bsrc[0]=bq; ta.bsrc[1]=bk; ta.bsrc[2]=bv; ta.bsrc[3]=bu; ta.bsrc[4]=bg;
    ta.bdst = pBc;
    ta.zsrc = z; ta.zdst = pZr;
    wtrans_kernel<<<dim3(32, 32, 11), dim3(32, 8)>>>(ta);            // 2 (incl. z round)

    // fused QKV                                                      // 3 <- ncu lands nearby
    tc_gemm<0,1><<<dim3(8, 32, 3), 256, SMEM>>>(pZr, rWq, pBc, pQKV,
        CD, CD, CD, CD,
        0, 0, 1048576, 0, (long)CM*CD, 0, 1024, 1,
        nullptr, nullptr, nullptr, nullptr);

    poolA_kernel<<<dim3(32, CB), 256>>>(z);                          // 4
    poolB_kernel<<<8, 256>>>();                                      // 5
    poolC_kernel<<<CM, 256>>>();                                     // 6
    ctab_kernel<<<(3 * CL * 512) / 256, 256>>>();                    // 7
    cvtV_kernel<<<CM*CD/1024, 256>>>(pV, pVh);                       // 8

    tc_gemm<0,1><<<gmain, 256, SMEM>>>(pPool, rWc, nullptr, pGk, CD, CD, CD, CD,
        0,0,0,0,0,0,0,1, nullptr, nullptr, nullptr, nullptr);

    // gate / nu hidden layers (into g_S scratch)
    tc_gemm<0,0><<<dim3(CHGATE/128, CM/128, 1), 256, SMEM>>>(pPool, rG1, rg_b1, pHg,
        CD, CD, CD, CHGATE, 0,0,0,0,0,0,0,1, nullptr, nullptr, nullptr, nullptr);
    tc_gemm<0,0><<<dim3(CHNU/128, CM/128, 1), 256, SMEM>>>(pPool, rN1, nu_b1, pHn,
        CD, CD, CD, CHNU, 0,0,0,0,0,0,0,1, nullptr, nullptr, nullptr, nullptr);
    gatenu_kernel<<<dim3(CM/8, 2), 256>>>(pHg, rg_w2, rg_b2, pHn, nu_w2, nu_b2,
                                          nu_diff, nu_adv);

    // coherence bias (causal blocks only): gb[b] = tanh(gamma)/32 * gk[b] @ K_raw[b]^T
    tc_gemm<2,0><<<dim3(CL/128, CL/128, CB), 256, SMEM>>>(pGk, pK, nullptr, pGb,
        CD, CD, CD, CL,
        (long)CL*CD, 0, (long)CL*CD, 0, (long)CL*CL, 0, 0, 1,
        nullptr, nullptr, gamma, nullptr);

    rope_all_kernel<<<(CM * 512) / 256, 256>>>(z, pQ, pK);

    // fused U/G
    tc_gemm<0,0><<<dim3(8, 32, 2), 256, SMEM>>>(pZg, rWu, pBc + 3*1024, pUG,
        CD, CD, CD, CD,
        0, 0, 1048576, 0, (long)CM*CD, 0, 1024, 1,
        nullptr, nullptr, nullptr, nullptr);

    // logits: S[b,h] = 0.125 * Qr_h @ Kr_h^T + gb[b], causal block skip
    tc_gemm<3,0><<<dim3(CL/128, CL/128, CB*CNH), 256, SMEM>>>(pQ, pK, nullptr, pS,
        CHD, CD, CD, CL,
        (long)CL*CD, CHD, (long)CL*CD, CHD, (long)CL*CL, (long)CL*CL, 0, CNH,
        nullptr, nullptr, nullptr, pGb);

    smaw_kernel<<<dim3(CL, CB), 256>>>(out_aw);
    attn_pv<<<dim3(CL/128, CNH, CB), 256, SMEMP>>>(pVh);

    bilin_ln_kernel<<<CM, 256>>>(pU, pG, ln_w, ln_b);
    tc_gemm<1,0><<<gmain, 256, SMEM>>>(pU, rCw, Cb, out_z, CD, CD, CD, CD,
        0,0,0,0,0,0,0,1, z, pAo, nullptr, nullptr);
}

// round 14
// speedup vs baseline: 1.7143x; 1.0233x over previous
#include <cuda_runtime.h>
#include <cuda_bf16.h>
#include <math.h>
#include <stdint.h>

#define CB 2
#define CL 2048
#define CD 1024
#define CNH 16
#define CHD 64
#define CM (CB*CL)          // 4096 rows
#define CHGATE 256
#define CHNU 128

// ---------------- scratch (device globals; allocation-free rule) ----------------
__device__ float g_pool[CM*CD];
__device__ float g_QKV[3*CM*CD];  // Q | K | V
__device__ float g_UG[2*CM*CD];   // U | G (adv_n written back into U slice)
__device__ __nv_bfloat16 g_Vh[CM*CD]; // bf16 V for attn_pv
__device__ float g_gk[CM*CD];
__device__ float g_zglu[CM*CD];
__device__ float g_ao[CM*CD];     // attention output
__device__ float g_zr[CM*CD];     // tf32-rounded z
__device__ float g_Wr[7*1048576 + 393216]; // transposed+rounded weights [N,K]
__device__ float g_bcat[5*1024];  // bq|bk|bv|bu|bg
__device__ float g_gb[CB*CL*CL];  // coherence bias (causal blocks only)
__device__ float g_S[134217728];  // (B,NH,L,L) logits (fp32) -> probs (bf16 in-place)
__device__ float g_gate[CM];
__device__ float g_nu[CM];
__device__ float g_csum[CB*32*CD];// pool chunk sums
__device__ float g_ctab[3*CL*1024]; // rope tables: [base][t][cos512|sin512]
__device__ double g_invd[1536];   // inv freqs: [fast | slow | glu] x 512

// ---------------- helpers ----------------
__device__ __forceinline__ unsigned f2tf(float x) {
    unsigned r; asm("cvt.rna.tf32.f32 %0, %1;" : "=r"(r) : "f"(x)); return r;
}
__device__ __forceinline__ float tfr(float x) { return __uint_as_float(f2tf(x)); }
__device__ __forceinline__ void cpa16(float* s, const float* g) {
    unsigned sa = (unsigned)__cvta_generic_to_shared(s);
    asm volatile("cp.async.cg.shared.global [%0], [%1], 16;" :: "r"(sa), "l"(g));
}
__device__ __forceinline__ void cpa16b(void* s, const void* g) {
    unsigned sa = (unsigned)__cvta_generic_to_shared(s);
    asm volatile("cp.async.cg.shared.global [%0], [%1], 16;" :: "r"(sa), "l"(g));
}
__device__ __forceinline__ void mma8(float* d, const unsigned* a, const unsigned* b) {
    asm volatile(
        "mma.sync.aligned.m16n8k8.row.col.f32.tf32.tf32.f32 "
        "{%0,%1,%2,%3},{%4,%5,%6,%7},{%8,%9},{%0,%1,%2,%3};"
        : "+f"(d[0]), "+f"(d[1]), "+f"(d[2]), "+f"(d[3])
        : "r"(a[0]), "r"(a[1]), "r"(a[2]), "r"(a[3]), "r"(b[0]), "r"(b[1]));
}
__device__ __forceinline__ void mma16(float* d, const unsigned* a, const unsigned* b) {
    asm volatile(
        "mma.sync.aligned.m16n8k16.row.col.f32.bf16.bf16.f32 "
        "{%0,%1,%2,%3},{%4,%5,%6,%7},{%8,%9},{%0,%1,%2,%3};"
        : "+f"(d[0]), "+f"(d[1]), "+f"(d[2]), "+f"(d[3])
        : "r"(a[0]), "r"(a[1]), "r"(a[2]), "r"(a[3]), "r"(b[0]), "r"(b[1]));
}
__device__ __forceinline__ void ldsm4(unsigned* r, unsigned addr) {
    asm volatile("ldmatrix.sync.aligned.m8n8.x4.shared.b16 {%0,%1,%2,%3}, [%4];"
        : "=r"(r[0]), "=r"(r[1]), "=r"(r[2]), "=r"(r[3]) : "r"(addr));
}
__device__ __forceinline__ void ldsm4t(unsigned* r, unsigned addr) {
    asm volatile("ldmatrix.sync.aligned.m8n8.x4.trans.shared.b16 {%0,%1,%2,%3}, [%4];"
        : "=r"(r[0]), "=r"(r[1]), "=r"(r[2]), "=r"(r[3]) : "r"(addr));
}
__device__ __forceinline__ unsigned pack_bf(float a, float b) {
    __nv_bfloat162 h = __floats2bfloat162_rn(a, b);
    return *(unsigned*)&h;
}

// ---------------- weight transpose + round (+ bias concat z=9, z-round z=10) ----------------
struct TrArgs { const float* src[9]; float* dst[9]; int N[9];
                const float* bsrc[5]; float* bdst;
                const float* zsrc; float* zdst; };
__global__ void wtrans_kernel(TrArgs a) {
    const int w = blockIdx.z;
    if (w == 9) {
        int i = blockIdx.x;
        if (i < 5 && blockIdx.y == 0) {
            int t = threadIdx.y * 32 + threadIdx.x;
#pragma unroll
            for (int j = 0; j < 4; j++)
                a.bdst[i * 1024 + t + j * 256] = a.bsrc[i][t + j * 256];
        }
        return;
    }
    if (w == 10) {
        int blk = blockIdx.y * 32 + blockIdx.x;
        int t = threadIdx.y * 32 + threadIdx.x;
        size_t base = (size_t)blk * 4096 + t;
#pragma unroll
        for (int j = 0; j < 16; j++)
            a.zdst[base + j * 256] = tfr(a.zsrc[base + j * 256]);
        return;
    }
    const int N = a.N[w];
    const int nx = blockIdx.x * 32;
    if (nx >= N) return;
    const int ky = blockIdx.y * 32;
    __shared__ float t[32][33];
    const float* src = a.src[w];
    const int tx = threadIdx.x, ty = threadIdx.y;   // 32 x 8
#pragma unroll
    for (int i = 0; i < 4; i++)
        t[ty + 8*i][tx] = src[(size_t)(ky + ty + 8*i) * N + nx + tx];
    __syncthreads();
    float* dst = a.dst[w];
#pragma unroll
    for (int i = 0; i < 4; i++)
        dst[(size_t)(nx + ty + 8*i) * 1024 + ky + tx] = tfr(t[tx][ty + 8*i]);
}

__global__ void cvtV_kernel(const float* __restrict__ v, __nv_bfloat16* __restrict__ o) {
    int i = blockIdx.x * 256 + threadIdx.x;
    float4 x = ((const float4*)v)[i];
    uint2 u;
    u.x = pack_bf(x.x, x.y);
    u.y = pack_bf(x.z, x.w);
    ((uint2*)o)[i] = u;
}

// ---------------- tensor-core GEMM: 128x128x32 tiles, tf32, full-LDSM, 3-stage ----------------
// C = A[M,K] @ B[N,K]^T   (both operands K-major)
// MODE 0: C = acc + bias(optional, +z*sBz); RND rounds output to tf32
// MODE 1: C = r1 + 0.42*r2 + 1.07*(acc + bias)
// MODE 2: C = tanh(gamma)/32 * acc, causal blockskip
// MODE 3: C = 0.125*acc + gb[l,m], causal blockskip
template<int MODE, int RND>
__global__ __launch_bounds__(256, 2) void tc_gemm(
    const float* __restrict__ A, const float* __restrict__ Bm,
    const float* __restrict__ bias, float* __restrict__ C,
    int K, int lda, int ldb, int ldc,
    long sAo, long sAi, long sBo, long sBi, long sCz, long sGo, long sBz, int zdiv,
    const float* __restrict__ r1, const float* __restrict__ r2,
    const float* __restrict__ gamma, const float* __restrict__ gbb)
{
    const int bm = blockIdx.y * 128, bn = blockIdx.x * 128;
    if ((MODE == 2 || MODE == 3) && bn >= bm + 128) return;   // causal-dead block
    const int z = blockIdx.z;
    const int zo = z / zdiv, zi = z - zo * zdiv;
    A  += (size_t)zo * sAo + (size_t)zi * sAi;
    Bm += (size_t)zo * sBo + (size_t)zi * sBi;
    C  += (size_t)z * sCz;
    if (bias) bias += (size_t)z * sBz;
    const float* gbp = (MODE == 3) ? (gbb + (size_t)zo * sGo) : nullptr;

    extern __shared__ float sm[];
    const int STG = 9216;                     // floats per stage (A 4608 | B 4608)

    const int t = threadIdx.x;
    const int wid = t >> 5, lane = t & 31;
    const int wm = (wid >> 2) * 64, wn = (wid & 3) * 32;
    const int g = lane >> 2, tig = lane & 3;

    const unsigned aoff = ((lane & 15) * 36 + (lane >> 4) * 4) * 4;
    const unsigned boff = ((lane & 7) * 36 + ((lane >> 3) & 1) * 4 + (lane >> 4) * (8 * 36)) * 4;

    float acc[4][4][4];
#pragma unroll
    for (int i = 0; i < 4; i++)
#pragma unroll
        for (int j = 0; j < 4; j++)
#pragma unroll
            for (int q = 0; q < 4; q++) acc[i][j][q] = 0.f;

    auto loadT = [&](float* s, const float* G, int ld, int base, int k0) {
        int r = t >> 3, k4 = (t & 7) * 4;
#pragma unroll
        for (int it = 0; it < 4; it++)
            cpa16(s + (r + it*32)*36 + k4,
                  G + (size_t)(base + r + it*32) * ld + k0 + k4);
    };
    auto loadStage = [&](int s, int kt) {
        loadT(sm + s*STG,        A,  lda, bm, kt*32);
        loadT(sm + s*STG + 4608, Bm, ldb, bn, kt*32);
        asm volatile("cp.async.commit_group;");
    };

    const int NT = K >> 5;
    loadStage(0, 0);
    if (NT > 1) loadStage(1, 1);

    int cs = 0, ns = (NT > 1) ? 2 : 1;        // compute stage, next-load stage
    for (int kt = 0; kt < NT; kt++) {
        if (kt + 1 < NT) asm volatile("cp.async.wait_group 1;");
        else             asm volatile("cp.async.wait_group 0;");
        __syncthreads();                       // compute(kt-1) reads done; stage kt ready
        if (kt + 2 < NT) {
            loadStage(ns, kt + 2);
            ns = (ns == 2) ? 0 : ns + 1;
        }
        const unsigned Au = (unsigned)__cvta_generic_to_shared(sm + cs*STG);
        const unsigned Bu = Au + 4608*4;
        cs = (cs == 2) ? 0 : cs + 1;
#pragma unroll
        for (int ks = 0; ks < 4; ks++) {
            const int k = ks * 8;
            unsigned af[4][4];
#pragma unroll
            for (int i = 0; i < 4; i++)
                ldsm4(af[i], Au + ((wm + 16*i) * 36 + k) * 4 + aoff);
            unsigned bf[4][2];
#pragma unroll
            for (int jj = 0; jj < 2; jj++) {
                unsigned r4[4];
                ldsm4(r4, Bu + ((wn + 16*jj) * 36 + k) * 4 + boff);
                bf[2*jj][0]   = r4[0];
                bf[2*jj][1]   = r4[1];
                bf[2*jj+1][0] = r4[2];
                bf[2*jj+1][1] = r4[3];
            }
#pragma unroll
            for (int i = 0; i < 4; i++)
#pragma unroll
                for (int j = 0; j < 4; j++)
                    mma8(acc[i][j], af[i], bf[j]);
        }
    }

    float scale = 1.f;
    if (MODE == 2) scale = tanhf(gamma[0]) * 0.03125f;
    if (MODE == 3) scale = 0.125f;
#pragma unroll
    for (int i = 0; i < 4; i++) {
        const int r0 = bm + wm + 16*i + g;
#pragma unroll
        for (int j = 0; j < 4; j++) {
            const int c0 = bn + wn + 8*j + 2*tig;
#pragma unroll
            for (int h2 = 0; h2 < 2; h2++) {
                const int rr = r0 + h2*8;
                float v0 = acc[i][j][h2*2], v1 = acc[i][j][h2*2+1];
                const size_t off = (size_t)rr * ldc + c0;
                if (MODE == 0) {
                    if (bias) { v0 += bias[c0]; v1 += bias[c0+1]; }
                    if (RND) { v0 = tfr(v0); v1 = tfr(v1); }
                    C[off] = v0; C[off+1] = v1;
                } else if (MODE == 1) {
                    C[off]   = r1[off]   + 0.42f*r2[off]   + 1.07f*(v0 + bias[c0]);
                    C[off+1] = r1[off+1] + 0.42f*r2[off+1] + 1.07f*(v1 + bias[c0+1]);
                } else if (MODE == 2) {
                    C[off] = tfr(v0*scale); C[off+1] = tfr(v1*scale);
                } else {
                    const size_t go = (size_t)rr * CL + c0;
                    C[off]   = v0*scale + gbp[go];
                    C[off+1] = v1*scale + gbp[go+1];
                }
            }
        }
    }
}

// ---------------- attn_out = P(bf16) @ V(bf16), m16n8k16 MMA, causal, 3-stage ----------------
__global__ __launch_bounds__(256) void attn_pv(const __nv_bfloat16* __restrict__ Vh) {
    const int l0 = blockIdx.x * 128;
    const int h = blockIdx.y, b = blockIdx.z;
    const char* Sb = (const char*)g_S + (((size_t)(b * CNH + h) * CL + l0) * CL) * 4;
    const __nv_bfloat16* V = Vh + (size_t)b * CL * CD + h * CHD;
    float* O = g_ao + (size_t)b * CL * CD + h * CHD;

    extern __shared__ char smc[];
    const int STG = 14848;                    // S 128*80 + V 32*144

    const int t = threadIdx.x;
    const int wid = t >> 5, lane = t & 31;
    const int wm = wid * 16;
    const int g = lane >> 2, tig = lane & 3;
    const int mrow = ((lane >> 3) & 1) * 8 + (lane & 7);
    const int mcb  = ((lane >> 4) & 1) * 16;

    float acc[8][4];
#pragma unroll
    for (int j = 0; j < 8; j++)
#pragma unroll
        for (int q = 0; q < 4; q++) acc[j][q] = 0.f;

    auto loadStage = [&](int s, int k0) {
        char* sp = smc + s * STG;
#pragma unroll
        for (int j = 0; j < 2; j++) {
            int a = t * 2 + j;
            int row = a >> 2, ch = a & 3;
            cpa16b(sp + row * 80 + ch * 16,
                   Sb + (size_t)row * CL * 4 + k0 * 2 + ch * 16);
        }
        char* vp = sp + 10240;
        int row = t >> 3, ch = t & 7;
        cpa16b(vp + row * 144 + ch * 16,
               (const char*)(V + (size_t)(k0 + row) * CD) + ch * 16);
        asm volatile("cp.async.commit_group;");
    };

    const int NT = (l0 + 128) >> 5;
    loadStage(0, 0);
    if (NT > 1) loadStage(1, 32);

    int cs = 0, ns = (NT > 1) ? 2 : 1;
    for (int kt = 0; kt < NT; kt++) {
        if (kt + 1 < NT) asm volatile("cp.async.wait_group 1;");
        else             asm volatile("cp.async.wait_group 0;");
        __syncthreads();
        if (kt + 2 < NT) {
            loadStage(ns, (kt + 2) * 32);
            ns = (ns == 2) ? 0 : ns + 1;
        }
        const unsigned Su = (unsigned)__cvta_generic_to_shared(smc + cs*STG);
        const unsigned Vu = Su + 10240;
        cs = (cs == 2) ? 0 : cs + 1;
#pragma unroll
        for (int ks = 0; ks < 2; ks++) {
            unsigned af[4];
            ldsm4(af, Su + (wm + mrow) * 80 + ks * 32 + mcb);
            unsigned bf[8][2];
#pragma unroll
            for (int nt = 0; nt < 4; nt++) {
                unsigned r4[4];
                ldsm4t(r4, Vu + (ks * 16 + mrow) * 144 + nt * 32 + mcb);
                bf[2*nt][0]   = r4[0];
                bf[2*nt][1]   = r4[1];
                bf[2*nt+1][0] = r4[2];
                bf[2*nt+1][1] = r4[3];
            }
#pragma unroll
            for (int j = 0; j < 8; j++)
                mma16(acc[j], af, bf[j]);
        }
    }
#pragma unroll
    for (int j = 0; j < 8; j++) {
        const int c0 = 8*j + 2*tig;
#pragma unroll
        for (int h2 = 0; h2 < 2; h2++) {
            const int rr = l0 + wm + g + h2*8;
            O[(size_t)rr * CD + c0]     = acc[j][h2*2];
            O[(size_t)rr * CD + c0 + 1] = acc[j][h2*2 + 1];
        }
    }
}

// ---------------- rope helpers ----------------
__global__ void inv_kernel() {
    int d = threadIdx.x;
    double e = (double)(2 * d) / (double)CD;
    g_invd[d]        = pow(1.6180339887498948482, -e);
    g_invd[512 + d]  = pow(1618.0, -e);
    g_invd[1024 + d] = pow(16180.0, -e);
}

__device__ __forceinline__ void rope_cs(double inv, int t, float* c, float* s) {
    double ang = (double)t * inv;
    double k = floor(ang * 0.15915494309189533576888376337251436);
    float a = (float)(ang - k * 6.28318530717958647692528676655900577);
    sincosf(a, s, c);
}

__global__ void ctab_kernel() {
    int idx = blockIdx.x * blockDim.x + threadIdx.x;
    int d = idx & 511;
    int t = (idx >> 9) & (CL - 1);
    int base = idx >> 20;
    float c, s;
    rope_cs(g_invd[base * 512 + d], t, &c, &s);
    float* o = g_ctab + (size_t)base * CL * 1024 + t * 1024;
    o[d] = c;
    o[d + 512] = s;
}

// ---------------- causal cumulative mean: 3-phase parallel scan ----------------
__global__ void poolA_kernel(const float* __restrict__ z) {
    const int c = blockIdx.x, b = blockIdx.y;
    const int t = threadIdx.x;
    const float4* zp = (const float4*)(z + ((size_t)b * CL + c * 64) * CD);
    float4* pp = (float4*)(g_pool + ((size_t)b * CL + c * 64) * CD);
    float4 acc = make_float4(0.f, 0.f, 0.f, 0.f);
    for (int r = 0; r < 64; r++) {
        float4 v = zp[r * 256 + t];
        acc.x += v.x; acc.y += v.y; acc.z += v.z; acc.w += v.w;
        pp[r * 256 + t] = acc;
    }
    ((float4*)g_csum)[((size_t)b * 32 + c) * 256 + t] = acc;
}
__global__ void poolB_kernel() {
    int idx = blockIdx.x * 256 + threadIdx.x;
    int b = idx >> 10, d = idx & 1023;
    float run = 0.f;
    for (int c = 0; c < 32; c++) {
        size_t o = ((size_t)b * 32 + c) * CD + d;
        float v = g_csum[o];
        g_csum[o] = run;
        run += v;
    }
}
__global__ void poolC_kernel() {
    size_t idx = (size_t)blockIdx.x * 256 + threadIdx.x;
    int row = (int)(idx >> 8);
    int f4 = (int)(idx & 255);
    int b = row >> 11, l = row & (CL - 1), c = l >> 6;
    float4 off = ((const float4*)g_csum)[((size_t)(b * 32 + c)) * 256 + f4];
    float4 v = ((float4*)g_pool)[idx];
    float inv = 1.f / (float)(l + 1);
    v.x = tfr((v.x + off.x) * inv);
    v.y = tfr((v.y + off.y) * inv);
    v.z = tfr((v.z + off.z) * inv);
    v.w = tfr((v.w + off.w) * inv);
    ((float4*)g_pool)[idx] = v;
}

// ---------------- merged gate/nu epilogue ----------------
__global__ __launch_bounds__(256) void gatenu_kernel(
    const float* __restrict__ ghid, const float* __restrict__ gw2, const float* __restrict__ gb2,
    const float* __restrict__ nhid, const float* __restrict__ nw2, const float* __restrict__ nb2,
    const float* __restrict__ nu_diff, const float* __restrict__ nu_adv)
{
    int row = blockIdx.x * 8 + (threadIdx.x >> 5);
    int lane = threadIdx.x & 31;
    if (blockIdx.y == 0) {
        const float* hr = ghid + (size_t)row * CHGATE;
        float acc = 0.f;
#pragma unroll
        for (int j = 0; j < 8; j++) {
            int c = lane + j * 32;
            float x = hr[c];
            float h = 0.5f * x * (1.f + erff(x * 0.7071067811865476f));
            acc += h * gw2[c];
        }
#pragma unroll
        for (int o = 16; o > 0; o >>= 1) acc += __shfl_xor_sync(~0u, acc, o);
        if (lane == 0) {
            float y = acc + gb2[0];
            g_gate[row] = 1.f / (1.f + expf(-y));
        }
    } else {
        const float* hr = nhid + (size_t)row * CHNU;
        float acc = 0.f;
#pragma unroll
        for (int j = 0; j < 4; j++) {
            int c = lane + j * 32;
            acc += tanhf(hr[c]) * nw2[c];
        }
#pragma unroll
        for (int o = 16; o > 0; o >>= 1) acc += __shfl_xor_sync(~0u, acc, o);
        if (lane == 0) {
            g_nu[row] = fabsf(nu_diff[0]) + tanhf(acc + nb2[0]) * fabsf(nu_adv[0]);
        }
    }
}

// ---------------- merged RoPE from tables: Q/K in-place + zglu write ----------------
__global__ void rope_all_kernel(const float* __restrict__ z,
                                float* __restrict__ Q, float* __restrict__ K) {
    int idx = blockIdx.x * blockDim.x + threadIdx.x;
    if (idx >= CM * 512) return;
    int d = idx & 511;
    int row = idx >> 9;
    int t = row & (CL - 1);
    float g = g_gate[row];
    const float* tf = g_ctab + (size_t)t * 1024 + d;
    const float* ts = tf + (size_t)CL * 1024;
    const float* tg = ts + (size_t)CL * 1024;
    float c = g * tf[0] + (1.f - g) * ts[0];
    float s = g * tf[512] + (1.f - g) * ts[512];
    float cg = tg[0], sg = tg[512];
    size_t lo = (size_t)row * CD + d, hi = lo + 512;
    float ql = Q[lo], qh = Q[hi];
    Q[lo] = tfr(ql * c - qh * s);
    Q[hi] = tfr(qh * c + ql * s);
    float kl = K[lo], kh = K[hi];
    K[lo] = tfr(kl * c - kh * s);
    K[hi] = tfr(kh * c + kl * s);
    float xl = z[lo], xh = z[hi];
    g_zglu[lo] = tfr(xl * cg - xh * sg);
    g_zglu[hi] = tfr(xh * cg + xl * sg);
}

// ---------------- fused causal softmax (16 heads serial) + head-mean; bf16 probs ----------------
__global__ __launch_bounds__(256) void smaw_kernel(float* __restrict__ aw) {
    const int l = blockIdx.x;
    const int b = blockIdx.y;
    const int n = l + 1;
    const int bound = ((l >> 7) + 1) << 7;
    const int tid = threadIdx.x;
    const int lane = tid & 31, wid = tid >> 5;
    __shared__ float red[8];
    float4 awacc[2];
    awacc[0] = make_float4(0.f, 0.f, 0.f, 0.f);
    awacc[1] = make_float4(0.f, 0.f, 0.f, 0.f);
    const float NEG = -3.4e38f;

    for (int h = 0; h < CNH; h++) {
        float* row = g_S + ((size_t)(b * CNH + h) * CL + l) * CL;
        float4* row4 = (float4*)row;
        uint2* rowh2 = (uint2*)row;
        float4 v[2];
        float mx = NEG;
#pragma unroll
        for (int ii = 0; ii < 2; ii++) {
            int f4 = tid + ii * 256;
            int c0 = f4 * 4;
            if (c0 < n) {
                float4 tv = row4[f4];
                if (c0 + 1 >= n) tv.y = NEG;
                if (c0 + 2 >= n) tv.z = NEG;
                if (c0 + 3 >= n) tv.w = NEG;
                v[ii] = tv;
            } else {
                v[ii] = make_float4(NEG, NEG, NEG, NEG);
            }
            mx = fmaxf(mx, fmaxf(fmaxf(v[ii].x, v[ii].y), fmaxf(v[ii].z, v[ii].w)));
        }
#pragma unroll
        for (int o = 16; o > 0; o >>= 1) mx = fmaxf(mx, __shfl_xor_sync(~0u, mx, o));
        if (lane == 0) red[wid] = mx;
        __syncthreads();
        mx = red[0];
#pragma unroll
        for (int w = 1; w < 8; w++) mx = fmaxf(mx, red[w]);
        __syncthreads();

        float sum = 0.f;
#pragma unroll
        for (int ii = 0; ii < 2; ii++) {
            v[ii].x = expf(v[ii].x - mx);
            v[ii].y = expf(v[ii].y - mx);
            v[ii].z = expf(v[ii].z - mx);
            v[ii].w = expf(v[ii].w - mx);
            sum += v[ii].x + v[ii].y + v[ii].z + v[ii].w;
        }
#pragma unroll
        for (int o = 16; o > 0; o >>= 1) sum += __shfl_xor_sync(~0u, sum, o);
        if (lane == 0) red[wid] = sum;
        __syncthreads();
        sum = red[0];
#pragma unroll
        for (int w = 1; w < 8; w++) sum += red[w];
        __syncthreads();
        float rinv = 1.f / sum;

#pragma unroll
        for (int ii = 0; ii < 2; ii++) {
            int f4 = tid + ii * 256;
            int c0 = f4 * 4;
            if (c0 < bound) {
                float4 p;
                p.x = v[ii].x * rinv; p.y = v[ii].y * rinv;
                p.z = v[ii].z * rinv; p.w = v[ii].w * rinv;
                awacc[ii].x += p.x; awacc[ii].y += p.y;
                awacc[ii].z += p.z; awacc[ii].w += p.w;
                uint2 pk;
                pk.x = pack_bf(p.x, p.y);
                pk.y = pack_bf(p.z, p.w);
                rowh2[f4] = pk;
            }
        }
        __syncthreads();
    }
    float4* awr4 = (float4*)(aw + ((size_t)b * CL + l) * CL);
    const float s16 = 1.f / CNH;
#pragma unroll
    for (int ii = 0; ii < 2; ii++) {
        int f4 = tid + ii * 256;
        float4 o;
        o.x = awacc[ii].x * s16; o.y = awacc[ii].y * s16;
        o.z = awacc[ii].z * s16; o.w = awacc[ii].w * s16;
        awr4[f4] = o;
    }
}

// ---------------- bilinear * (-nu) + LayerNorm (rounded out) ----------------
__global__ __launch_bounds__(256) void bilin_ln_kernel(
    float* __restrict__ U, const float* __restrict__ G,
    const float* __restrict__ ln_w, const float* __restrict__ ln_b)
{
    int row = blockIdx.x;
    int tid = threadIdx.x;
    size_t off = (size_t)row * CD;
    float nu = g_nu[row];
    __shared__ float red[256], red2[256];
    float a[4]; float s = 0.f, s2 = 0.f;
#pragma unroll
    for (int i = 0; i < 4; i++) {
        int d = tid + i * 256;
        float v = -nu * U[off + d] * G[off + d];
        a[i] = v; s += v; s2 += v * v;
    }
    red[tid] = s; red2[tid] = s2; __syncthreads();
    for (int st = 128; st > 0; st >>= 1) {
        if (tid < st) { red[tid] += red[tid + st]; red2[tid] += red2[tid + st]; }
        __syncthreads();
    }
    float mu = red[0] * (1.f / CD);
    float var = red2[0] * (1.f / CD) - mu * mu;
    float rstd = rsqrtf(var + 1e-5f);
#pragma unroll
    for (int i = 0; i < 4; i++) {
        int d = tid + i * 256;
        U[off + d] = tfr((a[i] - mu) * rstd * ln_w[d] + ln_b[d]);
    }
}

// ---------------- launcher (single stream; R12 schedule) ----------------
extern "C" void kernel_launch(void* const* d_in, const int* in_sizes, int n_in,
                              void* d_out, int out_size) {
    (void)in_sizes; (void)n_in; (void)out_size;
    const float* z     = (const float*)d_in[0];
    const float* Wq    = (const float*)d_in[1];
    const float* bq    = (const float*)d_in[2];
    const float* Wk    = (const float*)d_in[3];
    const float* bk    = (const float*)d_in[4];
    const float* Wv    = (const float*)d_in[5];
    const float* bv    = (const float*)d_in[6];
    const float* Wcoh  = (const float*)d_in[7];
    const float* gamma = (const float*)d_in[8];
    const float* rg_w1 = (const float*)d_in[9];
    const float* rg_b1 = (const float*)d_in[10];
    const float* rg_w2 = (const float*)d_in[11];
    const float* rg_b2 = (const float*)d_in[12];
    const float* nu_diff = (const float*)d_in[13];
    const float* nu_adv  = (const float*)d_in[14];
    const float* nu_w1 = (const float*)d_in[15];
    const float* nu_b1 = (const float*)d_in[16];
    const float* nu_w2 = (const float*)d_in[17];
    const float* nu_b2 = (const float*)d_in[18];
    const float* Wu    = (const float*)d_in[19];
    const float* bu    = (const float*)d_in[20];
    const float* Wg    = (const float*)d_in[21];
    const float* bg    = (const float*)d_in[22];
    const float* ln_w  = (const float*)d_in[23];
    const float* ln_b  = (const float*)d_in[24];
    const float* Cw    = (const float*)d_in[25];
    const float* Cb    = (const float*)d_in[26];

    float* out_z  = (float*)d_out;
    float* out_aw = out_z + (size_t)CM * CD;

    void* tmp;
    cudaGetSymbolAddress(&tmp, g_pool); float* pPool = (float*)tmp;
    cudaGetSymbolAddress(&tmp, g_QKV);  float* pQKV  = (float*)tmp;
    cudaGetSymbolAddress(&tmp, g_UG);   float* pUG   = (float*)tmp;
    cudaGetSymbolAddress(&tmp, g_Vh);   __nv_bfloat16* pVh = (__nv_bfloat16*)tmp;
    cudaGetSymbolAddress(&tmp, g_gk);   float* pGk   = (float*)tmp;
    cudaGetSymbolAddress(&tmp, g_zglu); float* pZg   = (float*)tmp;
    cudaGetSymbolAddress(&tmp, g_ao);   float* pAo   = (float*)tmp;
    cudaGetSymbolAddress(&tmp, g_zr);   float* pZr   = (float*)tmp;
    cudaGetSymbolAddress(&tmp, g_Wr);   float* pWr   = (float*)tmp;
    cudaGetSymbolAddress(&tmp, g_bcat); float* pBc   = (float*)tmp;
    cudaGetSymbolAddress(&tmp, g_gb);   float* pGb   = (float*)tmp;
    cudaGetSymbolAddress(&tmp, g_S);    float* pS    = (float*)tmp;

    float* pQ = pQKV;
    float* pK = pQKV + (size_t)CM * CD;
    float* pV = pQKV + 2 * (size_t)CM * CD;
    float* pU = pUG;
    float* pG = pUG + (size_t)CM * CD;

    float* rWq = pWr;
    float* rWc = pWr + 3*1048576;
    float* rWu = pWr + 4*1048576;
    float* rCw = pWr + 6*1048576;
    float* rG1 = pWr + 7*1048576;
    float* rN1 = pWr + 7*1048576 + 262144;

    float* pHg = pS;
    float* pHn = pS + (size_t)CM * CHGATE;

    const size_t SMEM  = 3 * 9216 * sizeof(float);   // 110592 (3-stage)
    const size_t SMEMP = 3 * 14848;                  // 44544 (attn_pv, 3-stage)
    cudaFuncSetAttribute(tc_gemm<0,0>, cudaFuncAttributeMaxDynamicSharedMemorySize, (int)SMEM);
    cudaFuncSetAttribute(tc_gemm<0,1>, cudaFuncAttributeMaxDynamicSharedMemorySize, (int)SMEM);
    cudaFuncSetAttribute(tc_gemm<1,0>, cudaFuncAttributeMaxDynamicSharedMemorySize, (int)SMEM);
    cudaFuncSetAttribute(tc_gemm<2,0>, cudaFuncAttributeMaxDynamicSharedMemorySize, (int)SMEM);
    cudaFuncSetAttribute(tc_gemm<3,0>, cudaFuncAttributeMaxDynamicSharedMemorySize, (int)SMEM);
    cudaFuncSetAttribute(attn_pv, cudaFuncAttributeMaxDynamicSharedMemorySize, (int)SMEMP);

    dim3 gmain(CD / 128, CM / 128, 1);

    inv_kernel<<<1, 512>>>();                                        // 1

    TrArgs ta;
    ta.src[0]=Wq;   ta.dst[0]=rWq;              ta.N[0]=1024;
    ta.src[1]=Wk;   ta.dst[1]=pWr + 1048576;    ta.N[1]=1024;
    ta.src[2]=Wv;   ta.dst[2]=pWr + 2*1048576;  ta.N[2]=1024;
    ta.src[3]=Wcoh; ta.dst[3]=rWc;              ta.N[3]=1024;
    ta.src[4]=Wu;   ta.dst[4]=rWu;              ta.N[4]=1024;
    ta.src[5]=Wg;   ta.dst[5]=pWr + 5*1048576;  ta.N[5]=1024;
    ta.src[6]=Cw;   ta.dst[6]=rCw;              ta.N[6]=1024;
    ta.src[7]=rg_w1;ta.dst[7]=rG1;              ta.N[7]=256;
    ta.src[8]=nu_w1;ta.dst[8]=rN1;              ta.N[8]=128;
    ta.bsrc[0]=bq; ta.bsrc[1]=bk; ta.bsrc[2]=bv; ta.bsrc[3]=bu; ta.bsrc[4]=bg;
    ta.bdst = pBc;
    ta.zsrc = z; ta.zdst = pZr;
    wtrans_kernel<<<dim3(32, 32, 11), dim3(32, 8)>>>(ta);            // 2

    // fused QKV                                                      // 3 <- ncu nearby
    tc_gemm<0,1><<<dim3(8, 32, 3), 256, SMEM>>>(pZr, rWq, pBc, pQKV,
        CD, CD, CD, CD,
        0, 0, 1048576, 0, (long)CM*CD, 0, 1024, 1,
        nullptr, nullptr, nullptr, nullptr);

    poolA_kernel<<<dim3(32, CB), 256>>>(z);                          // 4
    poolB_kernel<<<8, 256>>>();                                      // 5
    poolC_kernel<<<CM, 256>>>();                                     // 6
    ctab_kernel<<<(3 * CL * 512) / 256, 256>>>();                    // 7
    cvtV_kernel<<<CM*CD/1024, 256>>>(pV, pVh);                       // 8

    tc_gemm<0,1><<<gmain, 256, SMEM>>>(pPool, rWc, nullptr, pGk, CD, CD, CD, CD,
        0,0,0,0,0,0,0,1, nullptr, nullptr, nullptr, nullptr);

    // gate / nu hidden layers (into g_S scratch)
    tc_gemm<0,0><<<dim3(CHGATE/128, CM/128, 1), 256, SMEM>>>(pPool, rG1, rg_b1, pHg,
        CD, CD, CD, CHGATE, 0,0,0,0,0,0,0,1, nullptr, nullptr, nullptr, nullptr);
    tc_gemm<0,0><<<dim3(CHNU/128, CM/128, 1), 256, SMEM>>>(pPool, rN1, nu_b1, pHn,
        CD, CD, CD, CHNU, 0,0,0,0,0,0,0,1, nullptr, nullptr, nullptr, nullptr);
    gatenu_kernel<<<dim3(CM/8, 2), 256>>>(pHg, rg_w2, rg_b2, pHn, nu_w2, nu_b2,
                                          nu_diff, nu_adv);

    // coherence bias (causal blocks only): gb[b] = tanh(gamma)/32 * gk[b] @ K_raw[b]^T
    tc_gemm<2,0><<<dim3(CL/128, CL/128, CB), 256, SMEM>>>(pGk, pK, nullptr, pGb,
        CD, CD, CD, CL,
        (long)CL*CD, 0, (long)CL*CD, 0, (long)CL*CL, 0, 0, 1,
        nullptr, nullptr, gamma, nullptr);

    rope_all_kernel<<<(CM * 512) / 256, 256>>>(z, pQ, pK);

    // fused U/G
    tc_gemm<0,0><<<dim3(8, 32, 2), 256, SMEM>>>(pZg, rWu, pBc + 3*1024, pUG,
        CD, CD, CD, CD,
        0, 0, 1048576, 0, (long)CM*CD, 0, 1024, 1,
        nullptr, nullptr, nullptr, nullptr);

    // logits: S[b,h] = 0.125 * Qr_h @ Kr_h^T + gb[b], causal block skip
    tc_gemm<3,0><<<dim3(CL/128, CL/128, CB*CNH), 256, SMEM>>>(pQ, pK, nullptr, pS,
        CHD, CD, CD, CL,
        (long)CL*CD, CHD, (long)CL*CD, CHD, (long)CL*CL, (long)CL*CL, 0, CNH,
        nullptr, nullptr, nullptr, pGb);

    smaw_kernel<<<dim3(CL, CB), 256>>>(out_aw);
    attn_pv<<<dim3(CL/128, CNH, CB), 256, SMEMP>>>(pVh);

    bilin_ln_kernel<<<CM, 256>>>(pU, pG, ln_w, ln_b);
    tc_gemm<1,0><<<gmain, 256, SMEM>>>(pU, rCw, Cb, out_z, CD, CD, CD, CD,
        0,0,0,0,0,0,0,1, z, pAo, nullptr, nullptr);
}